// round 1
// baseline (speedup 1.0000x reference)
#include <cuda_runtime.h>
#include <math.h>

#define BB 4
#define NN 512
#define BQ (BB*NN)          // 2048
#define KBINS 48
#define PI_F 3.14159265358979f

// ---------------- device scratch (static, no allocation) ----------------
__device__ float g_X[BQ * 4704];          // binned features + dense row block (max IV=96)
__device__ float g_Xo[BQ * 96];           // obstacle bins (I=1)
__device__ float g_w  [BB*NN*NN];         // fluid pair weight
__device__ unsigned char g_kb [BB*NN*NN]; // fluid pair bin index
__device__ float g_wo [BB*NN*NN];         // obstacle pair weight
__device__ unsigned char g_kbo[BB*NN*NN];
__device__ float g_KS[837248];            // assembled steered-kernel GEMM matrices
__device__ float g_part[4*BQ*64];         // split-K partials
__device__ float g_outA[BQ*96];
__device__ float g_outB[BQ*96];
__device__ float g_feats[BQ*96];
__device__ float g_p1[BQ*2];
__device__ float g_v1[BQ*2];
__device__ float g_out4[BQ*2];

// KS matrix offsets (floats)
#define OFF1A 0          // rows 49*40=1960, cols 64  (conv_fluid cols 0..31, dense cols 32..63)
#define OFF1B 125440     // rows 48*2 =96,   cols 32  (conv_obst)
#define OFFL1 128512     // rows 49*96=4704, cols 64
#define OFFL2 429568     // rows 49*64=3136, cols 64
#define OFFL3 630272     // rows 3136, cols 64
#define OFFL4 830976     // rows 3136, cols 2

// ---------------- kernels ----------------

__global__ void k_prep(const float* __restrict__ p0, const float* __restrict__ v0,
                       const float* __restrict__ a, const float* __restrict__ other,
                       const float* __restrict__ v0enc)
{
    int i = blockIdx.x*blockDim.x + threadIdx.x;
    if (i >= BQ) return;
    float v0x = v0[i*2], v0y = v0[i*2+1];
    float v1x = v0x + 0.1f*a[i*2], v1y = v0y + 0.1f*a[i*2+1];
    float p1x = p0[i*2]   + 0.05f*(v0x+v1x);
    float p1y = p0[i*2+1] + 0.05f*(v0y+v1y);
    g_p1[i*2]=p1x; g_p1[i*2+1]=p1y;
    g_v1[i*2]=v1x; g_v1[i*2+1]=v1y;
    // fluid_feats (20 ch): [v1 | other_feats(3) | v0_enc(16)], ld = 40
    float* f = g_feats + i*40;
    f[0]=v1x; f[1]=v1y;
    #pragma unroll
    for (int c=0;c<3;c++){ f[2+c*2]=other[(i*3+c)*2]; f[3+c*2]=other[(i*3+c)*2+1]; }
    #pragma unroll
    for (int c=0;c<16;c++){ f[8+c*2]=v0enc[(i*16+c)*2]; f[9+c*2]=v0enc[(i*16+c)*2+1]; }
}

// pair geometry: bin index + window*mask weight
__global__ void k_geom(const float* __restrict__ src, const float* __restrict__ qry,
                       const float* __restrict__ mask, float* __restrict__ w,
                       unsigned char* __restrict__ kb)
{
    int idx = blockIdx.x*blockDim.x + threadIdx.x;
    if (idx >= BB*NN*NN) return;
    int s = idx & (NN-1);
    int q = (idx >> 9) & (NN-1);
    int b = idx >> 18;
    float rx = src[(b*NN+s)*2]   - qry[(b*NN+q)*2];
    float ry = src[(b*NN+s)*2+1] - qry[(b*NN+q)*2+1];
    float d2 = rx*rx + ry*ry;
    float m = mask[idx];
    float win = 1.0f - d2*(1.0f/1600.0f);
    float wv = 0.f; int kidx = 0;
    if (win > 0.f && m != 0.f) {
        wv = win*win*win*m;
        float dist = sqrtf(d2 + 1e-9f);
        int rb = (int)(dist*(3.0f/40.0f)); if (rb > 2) rb = 2;
        float th = atan2f(ry, rx);
        int tb = (int)floorf((th + PI_F)*(16.0f/(2.0f*PI_F)));
        tb &= 15;
        kidx = rb*16 + tb;
    }
    w[idx] = wv; kb[idx] = (unsigned char)kidx;
}

// assemble steered-kernel GEMM matrix: KS[row=(k,i,v) | dense (i,v)][col=(o,u)]
__global__ void k_steer(const float* __restrict__ Wc, const float* __restrict__ Ad,
                        const float* __restrict__ Bd, float* __restrict__ KS,
                        int O, int I, int cols, int convOff, int denseOff, int rows)
{
    int idx = blockIdx.x*blockDim.x + threadIdx.x;
    if (idx >= rows*cols) return;
    int row = idx / cols, col = idx % cols;
    int IV = 2*I;
    float val = 0.f;
    if (row < KBINS*IV) {
        if (Wc && col >= convOff && col < convOff + 2*O) {
            int k = row / IV, iv = row % IV, i = iv>>1, v = iv&1;
            int oc = col - convOff, o = oc>>1, u = oc&1;
            int t = k & 15;
            float th = (t + 0.5f)*(2.0f*PI_F/16.0f) - PI_F;
            float c = cosf(th), s = sinf(th);
            float R[2][2] = {{c,-s},{s,c}};
            const float* Wb = Wc + (((long long)k*O + o)*I + i)*4;
            val = R[u][0]*(Wb[0]*R[v][0] + Wb[1]*R[v][1])
                + R[u][1]*(Wb[2]*R[v][0] + Wb[3]*R[v][1]);
        }
    } else {
        int iv = row - KBINS*IV, i = iv>>1, v = iv&1;
        if (Ad && col >= denseOff && col < denseOff + 2*O) {
            int oc = col - denseOff, o = oc>>1, u = oc&1;
            if (u == v) val = Ad[o*I+i];
            else        val = (u==0) ? -Bd[o*I+i] : Bd[o*I+i];
        }
    }
    KS[row*cols + col] = val;
}

// fluid binning: one block per query; thread owns feature column iv, loops sources
template<int IV>
__global__ void k_bin(const float* __restrict__ feats)
{
    __shared__ float sM[KBINS*IV];
    __shared__ float sw[NN];
    __shared__ unsigned char sk[NN];
    int bq = blockIdx.x;
    int b = bq >> 9;
    int tid = threadIdx.x;
    const float* wrow = g_w + (long long)bq*NN;
    const unsigned char* krow = g_kb + (long long)bq*NN;
    for (int s = tid; s < NN; s += blockDim.x) { sw[s] = wrow[s]; sk[s] = krow[s]; }
    for (int i = tid; i < KBINS*IV; i += blockDim.x) sM[i] = 0.f;
    __syncthreads();
    if (tid < IV) {
        const float* fb = feats + (long long)(b*NN)*IV + tid;
        for (int s = 0; s < NN; ++s) {
            float ws = sw[s];               // warp-uniform
            if (ws != 0.f)
                sM[(int)sk[s]*IV + tid] += ws * fb[(long long)s*IV];
        }
    }
    __syncthreads();
    float* xr = g_X + (long long)bq*(49*IV);
    for (int i = tid; i < KBINS*IV; i += blockDim.x) xr[i] = sM[i];
    for (int i = tid; i < IV; i += blockDim.x)
        xr[KBINS*IV + i] = feats[(long long)bq*IV + i];
}

// obstacle binning: I=1 -> thread owns (k,v) output slot; deterministic order
__global__ void k_bino(const float* __restrict__ box_feats)
{
    __shared__ float sw[NN];
    __shared__ unsigned char sk[NN];
    __shared__ float sbf[NN*2];
    int bq = blockIdx.x; int b = bq >> 9; int tid = threadIdx.x;
    const float* wrow = g_wo + (long long)bq*NN;
    const unsigned char* krow = g_kbo + (long long)bq*NN;
    for (int s = tid; s < NN; s += blockDim.x) {
        sw[s] = wrow[s]; sk[s] = krow[s];
        sbf[s*2]   = box_feats[(b*NN+s)*2];
        sbf[s*2+1] = box_feats[(b*NN+s)*2+1];
    }
    __syncthreads();
    if (tid < 96) {
        int k = tid >> 1, v = tid & 1;
        float acc = 0.f;
        for (int s = 0; s < NN; ++s) {
            float ws = sw[s];
            if (ws != 0.f && (int)sk[s] == k) acc += ws * sbf[s*2+v];
        }
        g_Xo[bq*96 + tid] = acc;
    }
}

// split-K GEMM: [2048, inner] x [inner, cols<=64] -> part[split][2048][64]
#define GTM 32
#define GTK 8
__global__ void k_gemm(const float* __restrict__ X, const float* __restrict__ Wm,
                       int inner, int cols, int kb_per)
{
    int row0 = blockIdx.x * GTM;
    int k0 = blockIdx.y * kb_per * GTK;
    int k1 = min(inner, k0 + kb_per * GTK);
    __shared__ float Xs[GTK][GTM];
    __shared__ float Ws[GTK][64];
    int tid = threadIdx.x;            // 128
    int tx = tid & 15, ty = tid >> 4; // 16 col-groups x 8 row-groups
    float acc[4][4] = {};
    for (int kk = k0; kk < k1; kk += GTK) {
        {
            int e = tid;
            #pragma unroll
            for (int r = 0; r < 2; ++r, e += 128) {
                int k = e & 7, m = e >> 3;
                Xs[k][m] = X[(long long)(row0 + m)*inner + kk + k];
            }
        }
        {
            int e = tid;
            #pragma unroll
            for (int r = 0; r < 4; ++r, e += 128) {
                int k = e >> 6, c = e & 63;
                Ws[k][c] = (c < cols) ? Wm[(long long)(kk + k)*cols + c] : 0.f;
            }
        }
        __syncthreads();
        #pragma unroll
        for (int k = 0; k < GTK; ++k) {
            float4 av = *(const float4*)&Xs[k][ty*4];
            float4 bv = *(const float4*)&Ws[k][tx*4];
            acc[0][0] += av.x*bv.x; acc[0][1] += av.x*bv.y; acc[0][2] += av.x*bv.z; acc[0][3] += av.x*bv.w;
            acc[1][0] += av.y*bv.x; acc[1][1] += av.y*bv.y; acc[1][2] += av.y*bv.z; acc[1][3] += av.y*bv.w;
            acc[2][0] += av.z*bv.x; acc[2][1] += av.z*bv.y; acc[2][2] += av.z*bv.z; acc[2][3] += av.z*bv.w;
            acc[3][0] += av.w*bv.x; acc[3][1] += av.w*bv.y; acc[3][2] += av.w*bv.z; acc[3][3] += av.w*bv.w;
        }
        __syncthreads();
    }
    float* p = g_part + ((long long)blockIdx.y*BQ + row0)*64;
    #pragma unroll
    for (int i = 0; i < 4; ++i)
        #pragma unroll
        for (int j = 0; j < 4; ++j)
            p[(ty*4+i)*64 + tx*4+j] = acc[i][j];
}

// sum split-K partials (+ optional residual) into output buffer
__global__ void k_finish(float* __restrict__ out, int outLd, int colOff, int cols,
                         const float* __restrict__ res)
{
    int idx = blockIdx.x*blockDim.x + threadIdx.x;
    if (idx >= BQ*cols) return;
    int row = idx / cols, col = idx % cols;
    float v = 0.f;
    #pragma unroll
    for (int s = 0; s < 4; ++s) v += g_part[((long long)s*BQ + row)*64 + col];
    if (res) v += res[row*64 + col];
    out[row*outLd + colOff + col] = v;
}

// magnitude nonlinearity -> next layer's in_feats
__global__ void k_nonlin(const float* __restrict__ out, int C)
{
    int idx = blockIdx.x*blockDim.x + threadIdx.x;
    if (idx >= BQ*C) return;
    float x = out[idx*2], y = out[idx*2+1];
    float mag = x*x + y*y + 1e-6f;
    float sc = fmaxf(mag - 0.2f, 0.f) / mag;
    g_feats[idx*2]   = x*sc;
    g_feats[idx*2+1] = y*sc;
}

__global__ void k_final(const float* __restrict__ p0, float* __restrict__ dout, int half)
{
    int i = blockIdx.x*blockDim.x + threadIdx.x;
    if (i >= BQ) return;
    float cx = g_out4[i*2]  *(1.0f/128.0f);
    float cy = g_out4[i*2+1]*(1.0f/128.0f);
    float px = g_p1[i*2]   + cx;
    float py = g_p1[i*2+1] + cy;
    dout[i*2]   = px;
    dout[i*2+1] = py;
    dout[half + i*2]   = (px - p0[i*2])  *10.0f;
    dout[half + i*2+1] = (py - p0[i*2+1])*10.0f;
}

// ---------------- host driver ----------------
extern "C" void kernel_launch(void* const* d_in, const int* in_sizes, int n_in,
                              void* d_out, int out_size)
{
    const float* v0_enc = (const float*)d_in[1];
    const float* p0     = (const float*)d_in[2];
    const float* v0     = (const float*)d_in[3];
    const float* a      = (const float*)d_in[4];
    const float* other  = (const float*)d_in[5];
    const float* box    = (const float*)d_in[6];
    const float* boxf   = (const float*)d_in[7];
    const float* fmask  = (const float*)d_in[8];
    const float* bmask  = (const float*)d_in[9];
    const float* W_cf   = (const float*)d_in[10];
    const float* W_co   = (const float*)d_in[11];
    const float* A_df   = (const float*)d_in[12];
    const float* B_df   = (const float*)d_in[13];
    const float* W_c[4] = {(const float*)d_in[14], (const float*)d_in[17],
                           (const float*)d_in[20], (const float*)d_in[23]};
    const float* A_d[4] = {(const float*)d_in[15], (const float*)d_in[18],
                           (const float*)d_in[21], (const float*)d_in[24]};
    const float* B_d[4] = {(const float*)d_in[16], (const float*)d_in[19],
                           (const float*)d_in[22], (const float*)d_in[25]};
    float* dout = (float*)d_out;
    int half = out_size / 2;

    float *X, *Xo, *w, *wo, *KS, *outA, *outB, *feats, *p1, *out4;
    unsigned char *kb, *kbo;
    cudaGetSymbolAddress((void**)&X,    g_X);
    cudaGetSymbolAddress((void**)&Xo,   g_Xo);
    cudaGetSymbolAddress((void**)&w,    g_w);
    cudaGetSymbolAddress((void**)&kb,   g_kb);
    cudaGetSymbolAddress((void**)&wo,   g_wo);
    cudaGetSymbolAddress((void**)&kbo,  g_kbo);
    cudaGetSymbolAddress((void**)&KS,   g_KS);
    cudaGetSymbolAddress((void**)&outA, g_outA);
    cudaGetSymbolAddress((void**)&outB, g_outB);
    cudaGetSymbolAddress((void**)&feats,g_feats);
    cudaGetSymbolAddress((void**)&p1,   g_p1);
    cudaGetSymbolAddress((void**)&out4, g_out4);

    // 1. integrate + build fluid_feats (20 ch)
    k_prep<<<(BQ+127)/128, 128>>>(p0, v0, a, other, v0_enc);
    // 2. pair geometry (reused by all 5 fluid convs / 1 obstacle conv)
    k_geom<<<(BB*NN*NN)/256, 256>>>(p1, p1, fmask, w, kb);
    k_geom<<<(BB*NN*NN)/256, 256>>>(box, p1, bmask, wo, kbo);
    // 3. assemble all steered GEMM matrices
    {
        int r, c;
        r = 1960; c = 64;
        k_steer<<<(r*c+255)/256,256>>>(W_cf, A_df, B_df, KS+OFF1A, 16, 20, c, 0, 32, r);
        r = 96; c = 32;
        k_steer<<<(r*c+255)/256,256>>>(W_co, nullptr, nullptr, KS+OFF1B, 16, 1, c, 0, 0, r);
        r = 4704; c = 64;
        k_steer<<<(r*c+255)/256,256>>>(W_c[0], A_d[0], B_d[0], KS+OFFL1, 32, 48, c, 0, 0, r);
        r = 3136; c = 64;
        k_steer<<<(r*c+255)/256,256>>>(W_c[1], A_d[1], B_d[1], KS+OFFL2, 32, 32, c, 0, 0, r);
        k_steer<<<(r*c+255)/256,256>>>(W_c[2], A_d[2], B_d[2], KS+OFFL3, 32, 32, c, 0, 0, r);
        r = 3136; c = 2;
        k_steer<<<(r*c+255)/256,256>>>(W_c[3], A_d[3], B_d[3], KS+OFFL4, 1, 32, c, 0, 0, r);
    }
    dim3 gg(64, 4);
    // 4. stage 1: obstacle conv + fluid conv + dense -> outA (48 ch, ld 96)
    k_bino<<<BQ,128>>>(boxf);
    k_bin<40><<<BQ,128>>>(feats);
    k_gemm<<<gg,128>>>(X, KS+OFF1A, 1960, 64, (1960/8+3)/4);
    k_finish<<<(BQ*64+255)/256,256>>>(outA, 96, 32, 64, nullptr);
    k_gemm<<<gg,128>>>(Xo, KS+OFF1B, 96, 32, (96/8+3)/4);
    k_finish<<<(BQ*32+255)/256,256>>>(outA, 96, 0, 32, nullptr);
    // 5. layer 1: 48 -> 32, no residual -> outB
    k_nonlin<<<(BQ*48+255)/256,256>>>(outA, 48);
    k_bin<96><<<BQ,128>>>(feats);
    k_gemm<<<gg,128>>>(X, KS+OFFL1, 4704, 64, (4704/8+3)/4);
    k_finish<<<(BQ*64+255)/256,256>>>(outB, 64, 0, 64, nullptr);
    // 6. layer 2: 32 -> 32, residual outB -> outA
    k_nonlin<<<(BQ*32+255)/256,256>>>(outB, 32);
    k_bin<64><<<BQ,128>>>(feats);
    k_gemm<<<gg,128>>>(X, KS+OFFL2, 3136, 64, (3136/8+3)/4);
    k_finish<<<(BQ*64+255)/256,256>>>(outA, 64, 0, 64, outB);
    // 7. layer 3: 32 -> 32, residual outA -> outB
    k_nonlin<<<(BQ*32+255)/256,256>>>(outA, 32);
    k_bin<64><<<BQ,128>>>(feats);
    k_gemm<<<gg,128>>>(X, KS+OFFL3, 3136, 64, (3136/8+3)/4);
    k_finish<<<(BQ*64+255)/256,256>>>(outB, 64, 0, 64, outA);
    // 8. layer 4: 32 -> 1, no residual -> out4
    k_nonlin<<<(BQ*32+255)/256,256>>>(outB, 32);
    k_bin<64><<<BQ,128>>>(feats);
    k_gemm<<<gg,128>>>(X, KS+OFFL4, 3136, 2, (3136/8+3)/4);
    k_finish<<<(BQ*2+255)/256,256>>>(out4, 2, 0, 2, nullptr);
    // 9. apply correction
    k_final<<<(BQ+127)/128, 128>>>(p0, dout, half);
}

// round 2
// speedup vs baseline: 1.5874x; 1.5874x over previous
#include <cuda_runtime.h>
#include <math.h>

#define BB 4
#define NN 512
#define BQ 2048
#define KBINS 48
#define PI_F 3.14159265358979f

// ---------------- device scratch ----------------
__device__ __align__(16) float g_X[BQ * 4704];
__device__ __align__(16) float g_Xo[BQ * 96];
__device__ __align__(16) uint2 g_list [BQ * NN];
__device__ int   g_cnt [BQ];
__device__ __align__(16) uint2 g_listo[BQ * NN];
__device__ int   g_cnto[BQ];
__device__ __align__(16) float g_KS[838784];
__device__ __align__(16) float g_part[8 * BQ * 64];
__device__ __align__(16) float g_outA[BQ * 96];
__device__ __align__(16) float g_outB[BQ * 96];
__device__ __align__(16) float g_feats[BQ * 96];
__device__ float g_p1[BQ * 2];
__device__ float g_out4[BQ * 2];

// KS segment offsets (floats)
#define OFF1A 0        // rows 1984 (49*40 padded), cols 64
#define OFF1B 126976   // rows 96,   cols 32
#define OFFL1 130048   // rows 4704, cols 64
#define OFFL2 431104   // rows 3136, cols 64
#define OFFL3 631808   // rows 3136, cols 64
#define OFFL4 832512   // rows 3136, cols 2

// ---------------- kernels ----------------

__global__ void k_prep(const float* __restrict__ p0, const float* __restrict__ v0,
                       const float* __restrict__ a, const float* __restrict__ other,
                       const float* __restrict__ v0enc)
{
    int i = blockIdx.x*blockDim.x + threadIdx.x;
    if (i >= BQ) return;
    float v0x = v0[i*2], v0y = v0[i*2+1];
    float v1x = v0x + 0.1f*a[i*2], v1y = v0y + 0.1f*a[i*2+1];
    g_p1[i*2]   = p0[i*2]   + 0.05f*(v0x+v1x);
    g_p1[i*2+1] = p0[i*2+1] + 0.05f*(v0y+v1y);
    float* f = g_feats + i*40;
    f[0]=v1x; f[1]=v1y;
    #pragma unroll
    for (int c=0;c<3;c++){ f[2+c*2]=other[(i*3+c)*2]; f[3+c*2]=other[(i*3+c)*2+1]; }
    #pragma unroll
    for (int c=0;c<16;c++){ f[8+c*2]=v0enc[(i*16+c)*2]; f[9+c*2]=v0enc[(i*16+c)*2+1]; }
}

// fused geometry + compaction: one warp per query row, deterministic order by s
__global__ void k_compact(const float* __restrict__ src, const float* __restrict__ qry,
                          const float* __restrict__ mask,
                          uint2* __restrict__ list, int* __restrict__ cnt)
{
    int warp = (blockIdx.x*blockDim.x + threadIdx.x) >> 5;
    int lane = threadIdx.x & 31;
    if (warp >= BQ) return;
    int b = warp >> 9, q = warp & 511;
    float qx = qry[(b*NN+q)*2], qy = qry[(b*NN+q)*2+1];
    const float* mrow = mask + (size_t)warp*NN;
    uint2* lrow = list + (size_t)warp*NN;
    int base = 0;
    for (int c = 0; c < NN; c += 32) {
        int s = c + lane;
        float rx = src[(b*NN+s)*2]   - qx;
        float ry = src[(b*NN+s)*2+1] - qy;
        float d2 = rx*rx + ry*ry;
        float m = mrow[s];
        float win = 1.0f - d2*(1.0f/1600.0f);
        bool on = (win > 0.f) && (m != 0.f);
        float wv = 0.f; int kidx = 0;
        if (on) {
            wv = win*win*win*m;
            float dist = sqrtf(d2 + 1e-9f);
            int rb = (int)(dist*(3.0f/40.0f)); if (rb > 2) rb = 2;
            int tb = ((int)floorf((atan2f(ry,rx) + PI_F)*(16.0f/(2.0f*PI_F)))) & 15;
            kidx = rb*16 + tb;
        }
        unsigned mk = __ballot_sync(0xffffffffu, on);
        if (on) {
            int pos = base + __popc(mk & ((1u<<lane)-1u));
            lrow[pos] = make_uint2(__float_as_uint(wv), (unsigned)((kidx<<16) | s));
        }
        base += __popc(mk);
    }
    if (lane == 0) cnt[warp] = base;
}

// single-launch steered-kernel matrix assembly (6 segments)
struct SteerArgs { const float* Wc[6]; const float* Ad[6]; const float* Bd[6]; };
__device__ const int c_off[6]  = {OFF1A, OFF1B, OFFL1, OFFL2, OFFL3, OFFL4};
__device__ const int c_O[6]    = {16, 16, 32, 32, 32, 1};
__device__ const int c_I[6]    = {20, 1, 48, 32, 32, 32};
__device__ const int c_cols[6] = {64, 32, 64, 64, 64, 2};
__device__ const int c_dOff[6] = {32, -1, 0, 0, 0, 0};
__device__ const int c_rows[6] = {1984, 96, 4704, 3136, 3136, 3136};

__global__ void k_steer_all(SteerArgs args)
{
    int seg = blockIdx.y;
    int idx = blockIdx.x*blockDim.x + threadIdx.x;
    int rows = c_rows[seg], cols = c_cols[seg];
    if (idx >= rows*cols) return;
    int row = idx / cols, col = idx % cols;
    int O = c_O[seg], I = c_I[seg], IV = 2*I;
    float val = 0.f;
    if (row < KBINS*IV) {
        if (col < 2*O) {
            int k = row / IV, iv = row % IV, i = iv>>1, v = iv&1;
            int o = col>>1, u = col&1;
            int t = k & 15;
            float th = (t + 0.5f)*(2.0f*PI_F/16.0f) - PI_F;
            float c = cosf(th), s = sinf(th);
            float R[2][2] = {{c,-s},{s,c}};
            const float* Wb = args.Wc[seg] + (((long long)k*O + o)*I + i)*4;
            val = R[u][0]*(Wb[0]*R[v][0] + Wb[1]*R[v][1])
                + R[u][1]*(Wb[2]*R[v][0] + Wb[3]*R[v][1]);
        }
    } else if (row < KBINS*IV + IV) {
        int dOff = c_dOff[seg];
        if (dOff >= 0 && col >= dOff && col < dOff + 2*O) {
            int iv = row - KBINS*IV, i = iv>>1, v = iv&1;
            int oc = col - dOff, o = oc>>1, u = oc&1;
            if (u == v) val = args.Ad[seg][o*I+i];
            else        val = (u==0) ? -args.Bd[seg][o*I+i] : args.Bd[seg][o*I+i];
        }
    }
    g_KS[c_off[seg] + row*cols + col] = val;
}

// fluid binning over compacted list (branch-free loop)
template<int IV, int LD>
__global__ void k_bin(const float* __restrict__ feats)
{
    __shared__ float sM[KBINS*IV];
    __shared__ uint2 sl[NN];
    int bq = blockIdx.x, tid = threadIdx.x, b = bq >> 9;
    int cnt = g_cnt[bq];
    const uint2* lrow = g_list + (size_t)bq*NN;
    for (int i = tid; i < cnt; i += blockDim.x) sl[i] = lrow[i];
    for (int i = tid; i < KBINS*IV; i += blockDim.x) sM[i] = 0.f;
    __syncthreads();
    if (tid < IV) {
        const float* fb = feats + (size_t)(b*NN)*IV + tid;
        for (int e = 0; e < cnt; ++e) {
            uint2 pk = sl[e];
            float ws = __uint_as_float(pk.x);
            int s = pk.y & 0xffff, k = pk.y >> 16;
            sM[k*IV + tid] += ws * fb[(size_t)s*IV];
        }
    }
    __syncthreads();
    float* xr = g_X + (size_t)bq*LD;
    for (int i = tid; i < KBINS*IV; i += blockDim.x) xr[i] = sM[i];
    for (int i = tid; i < IV; i += blockDim.x)
        xr[KBINS*IV + i] = feats[(size_t)bq*IV + i];
    for (int i = 49*IV + tid; i < LD; i += blockDim.x) xr[i] = 0.f;
}

// obstacle binning (I=1): thread owns (k,v) slot, scans compacted list
__global__ void k_bino(const float* __restrict__ box_feats)
{
    __shared__ uint2 sl[NN];
    __shared__ float sbf[NN*2];
    int bq = blockIdx.x, tid = threadIdx.x, b = bq >> 9;
    int cnt = g_cnto[bq];
    const uint2* lrow = g_listo + (size_t)bq*NN;
    for (int i = tid; i < cnt; i += blockDim.x) sl[i] = lrow[i];
    for (int i = tid; i < NN*2; i += blockDim.x) sbf[i] = box_feats[b*NN*2 + i];
    __syncthreads();
    if (tid < 96) {
        int k = tid >> 1, v = tid & 1;
        float acc = 0.f;
        for (int e = 0; e < cnt; ++e) {
            uint2 pk = sl[e];
            if ((int)(pk.y >> 16) == k)
                acc += __uint_as_float(pk.x) * sbf[(pk.y & 0xffff)*2 + v];
        }
        g_Xo[bq*96 + tid] = acc;
    }
}

// split-K GEMM: [2048, inner] x [inner, cols<=64], BM=32 BN=64 BK=32, 128 thr
#define BM 32
#define BN 64
#define BK 32
__global__ void k_gemm(const float* __restrict__ X, const float* __restrict__ Wm,
                       int inner, int cols, int nsplit)
{
    int ntiles = inner / BK;
    int per = (ntiles + nsplit - 1) / nsplit;
    int t0 = blockIdx.y * per;
    int t1 = min(ntiles, t0 + per);
    int row0 = blockIdx.x * BM;
    __shared__ float Xs[BK][BM];
    __shared__ float Ws[BK][BN];
    int tid = threadIdx.x;
    int tx = tid & 15, ty = tid >> 4;
    float acc[4][4] = {};
    for (int t = t0; t < t1; ++t) {
        int kk = t*BK;
        {
            int m  = tid >> 3;
            int kq = (tid & 7)*4;
            #pragma unroll
            for (int r = 0; r < 2; ++r) {
                float4 v = *(const float4*)&X[(size_t)(row0 + m + r*16)*inner + kk + kq];
                Xs[kq+0][m+r*16] = v.x; Xs[kq+1][m+r*16] = v.y;
                Xs[kq+2][m+r*16] = v.z; Xs[kq+3][m+r*16] = v.w;
            }
        }
        {
            int k = tid >> 4;
            int c = (tid & 15)*4;
            #pragma unroll
            for (int r = 0; r < 4; ++r) {
                int kr = k + r*8;
                float4 v = (c < cols) ? *(const float4*)&Wm[(size_t)(kk+kr)*cols + c]
                                      : make_float4(0.f,0.f,0.f,0.f);
                *(float4*)&Ws[kr][c] = v;
            }
        }
        __syncthreads();
        #pragma unroll
        for (int k = 0; k < BK; ++k) {
            float4 av = *(const float4*)&Xs[k][ty*4];
            float4 bv = *(const float4*)&Ws[k][tx*4];
            acc[0][0] += av.x*bv.x; acc[0][1] += av.x*bv.y; acc[0][2] += av.x*bv.z; acc[0][3] += av.x*bv.w;
            acc[1][0] += av.y*bv.x; acc[1][1] += av.y*bv.y; acc[1][2] += av.y*bv.z; acc[1][3] += av.y*bv.w;
            acc[2][0] += av.z*bv.x; acc[2][1] += av.z*bv.y; acc[2][2] += av.z*bv.z; acc[2][3] += av.z*bv.w;
            acc[3][0] += av.w*bv.x; acc[3][1] += av.w*bv.y; acc[3][2] += av.w*bv.z; acc[3][3] += av.w*bv.w;
        }
        __syncthreads();
    }
    float* p = g_part + ((size_t)blockIdx.y*BQ + row0)*64;
    #pragma unroll
    for (int i = 0; i < 4; ++i) {
        float4 v = make_float4(acc[i][0], acc[i][1], acc[i][2], acc[i][3]);
        *(float4*)&p[(ty*4+i)*64 + tx*4] = v;
    }
}

// layer 4: cols=2 GEMV, one warp per output row, W in smem, shfl reduce
__global__ void k_gemv2(const float* __restrict__ X, const float* __restrict__ Wm, int inner)
{
    __shared__ float Wsh[3136*2];
    int tid = threadIdx.x;
    for (int i = tid; i < inner*2; i += blockDim.x) Wsh[i] = Wm[i];
    __syncthreads();
    int warp = tid >> 5, lane = tid & 31;
    int row = blockIdx.x*8 + warp;
    const float* xr = X + (size_t)row*inner;
    float a0 = 0.f, a1 = 0.f;
    for (int k = lane; k < inner; k += 32) {
        float x = xr[k];
        a0 += x*Wsh[k*2];
        a1 += x*Wsh[k*2+1];
    }
    #pragma unroll
    for (int o = 16; o; o >>= 1) {
        a0 += __shfl_down_sync(0xffffffffu, a0, o);
        a1 += __shfl_down_sync(0xffffffffu, a1, o);
    }
    if (lane == 0) { g_out4[row*2] = a0; g_out4[row*2+1] = a1; }
}

// sum split-K partials into output buffer (stage 1)
__global__ void k_finish(float* __restrict__ out, int outLd, int colOff, int cols, int nsplit)
{
    int idx = blockIdx.x*blockDim.x + threadIdx.x;
    if (idx >= BQ*cols) return;
    int row = idx / cols, col = idx % cols;
    float v = 0.f;
    for (int s = 0; s < nsplit; ++s) v += g_part[((size_t)s*BQ + row)*64 + col];
    out[row*outLd + colOff + col] = v;
}

// fused: sum partials + residual + nonlinearity (64-col layers)
__global__ void k_finnl(float* __restrict__ out, const float* __restrict__ res, int nsplit)
{
    int idx = blockIdx.x*blockDim.x + threadIdx.x;
    if (idx >= BQ*32) return;
    int row = idx >> 5, c = idx & 31;
    float x = 0.f, y = 0.f;
    for (int s = 0; s < nsplit; ++s) {
        const float* p = g_part + ((size_t)s*BQ + row)*64 + c*2;
        x += p[0]; y += p[1];
    }
    if (res) { x += res[row*64 + c*2]; y += res[row*64 + c*2+1]; }
    out[row*64 + c*2] = x; out[row*64 + c*2+1] = y;
    float mag = x*x + y*y + 1e-6f;
    float sc = fmaxf(mag - 0.2f, 0.f) / mag;
    g_feats[row*64 + c*2]   = x*sc;
    g_feats[row*64 + c*2+1] = y*sc;
}

// stage-1 nonlinearity (48 ch, ld 96)
__global__ void k_nonlin(const float* __restrict__ out, int C)
{
    int idx = blockIdx.x*blockDim.x + threadIdx.x;
    if (idx >= BQ*C) return;
    float x = out[idx*2], y = out[idx*2+1];
    float mag = x*x + y*y + 1e-6f;
    float sc = fmaxf(mag - 0.2f, 0.f) / mag;
    g_feats[idx*2]   = x*sc;
    g_feats[idx*2+1] = y*sc;
}

__global__ void k_final(const float* __restrict__ p0, float* __restrict__ dout, int half)
{
    int i = blockIdx.x*blockDim.x + threadIdx.x;
    if (i >= BQ) return;
    float px = g_p1[i*2]   + g_out4[i*2]  *(1.0f/128.0f);
    float py = g_p1[i*2+1] + g_out4[i*2+1]*(1.0f/128.0f);
    dout[i*2]   = px;
    dout[i*2+1] = py;
    dout[half + i*2]   = (px - p0[i*2])  *10.0f;
    dout[half + i*2+1] = (py - p0[i*2+1])*10.0f;
}

// ---------------- host driver ----------------
extern "C" void kernel_launch(void* const* d_in, const int* in_sizes, int n_in,
                              void* d_out, int out_size)
{
    const float* v0_enc = (const float*)d_in[1];
    const float* p0     = (const float*)d_in[2];
    const float* v0     = (const float*)d_in[3];
    const float* a      = (const float*)d_in[4];
    const float* other  = (const float*)d_in[5];
    const float* box    = (const float*)d_in[6];
    const float* boxf   = (const float*)d_in[7];
    const float* fmask  = (const float*)d_in[8];
    const float* bmask  = (const float*)d_in[9];
    float* dout = (float*)d_out;
    int half = out_size / 2;

    float *X, *Xo, *KS, *outA, *outB, *feats, *p1;
    uint2 *list, *listo; int *cnt, *cnto;
    cudaGetSymbolAddress((void**)&X,     g_X);
    cudaGetSymbolAddress((void**)&Xo,    g_Xo);
    cudaGetSymbolAddress((void**)&KS,    g_KS);
    cudaGetSymbolAddress((void**)&outA,  g_outA);
    cudaGetSymbolAddress((void**)&outB,  g_outB);
    cudaGetSymbolAddress((void**)&feats, g_feats);
    cudaGetSymbolAddress((void**)&p1,    g_p1);
    cudaGetSymbolAddress((void**)&list,  g_list);
    cudaGetSymbolAddress((void**)&listo, g_listo);
    cudaGetSymbolAddress((void**)&cnt,   g_cnt);
    cudaGetSymbolAddress((void**)&cnto,  g_cnto);

    SteerArgs sa;
    sa.Wc[0] = (const float*)d_in[10]; sa.Ad[0] = (const float*)d_in[12]; sa.Bd[0] = (const float*)d_in[13];
    sa.Wc[1] = (const float*)d_in[11]; sa.Ad[1] = nullptr;                sa.Bd[1] = nullptr;
    sa.Wc[2] = (const float*)d_in[14]; sa.Ad[2] = (const float*)d_in[15]; sa.Bd[2] = (const float*)d_in[16];
    sa.Wc[3] = (const float*)d_in[17]; sa.Ad[3] = (const float*)d_in[18]; sa.Bd[3] = (const float*)d_in[19];
    sa.Wc[4] = (const float*)d_in[20]; sa.Ad[4] = (const float*)d_in[21]; sa.Bd[4] = (const float*)d_in[22];
    sa.Wc[5] = (const float*)d_in[23]; sa.Ad[5] = (const float*)d_in[24]; sa.Bd[5] = (const float*)d_in[25];

    // 1. integrate + build 20-ch fluid feats
    k_prep<<<(BQ+127)/128, 128>>>(p0, v0, a, other, v0_enc);
    // 2. fused geometry + compaction (reused by all conv stages)
    k_compact<<<BQ/8, 256>>>(p1, p1, fmask, list, cnt);
    k_compact<<<BQ/8, 256>>>(box, p1, bmask, listo, cnto);
    // 3. assemble all steered GEMM matrices in one launch
    {
        dim3 g((301056 + 255)/256, 6);
        k_steer_all<<<g, 256>>>(sa);
    }
    // 4. stage 1: obstacle conv + fluid conv + dense -> outA (48 ch, ld 96)
    k_bino<<<BQ, 128>>>(boxf);
    k_bin<40,1984><<<BQ, 128>>>(feats);
    k_gemm<<<dim3(64,8), 128>>>(X, KS+OFF1A, 1984, 64, 8);
    k_finish<<<(BQ*64+255)/256, 256>>>(outA, 96, 32, 64, 8);
    k_gemm<<<dim3(64,1), 128>>>(Xo, KS+OFF1B, 96, 32, 1);
    k_finish<<<(BQ*32+255)/256, 256>>>(outA, 96, 0, 32, 1);
    k_nonlin<<<(BQ*48+255)/256, 256>>>(outA, 48);
    // 5. layer 1: 48 -> 32
    k_bin<96,4704><<<BQ, 128>>>(feats);
    k_gemm<<<dim3(64,8), 128>>>(X, KS+OFFL1, 4704, 64, 8);
    k_finnl<<<(BQ*32+255)/256, 256>>>(outB, nullptr, 8);
    // 6. layer 2: 32 -> 32, residual
    k_bin<64,3136><<<BQ, 128>>>(feats);
    k_gemm<<<dim3(64,8), 128>>>(X, KS+OFFL2, 3136, 64, 8);
    k_finnl<<<(BQ*32+255)/256, 256>>>(outA, outB, 8);
    // 7. layer 3: 32 -> 32, residual
    k_bin<64,3136><<<BQ, 128>>>(feats);
    k_gemm<<<dim3(64,8), 128>>>(X, KS+OFFL3, 3136, 64, 8);
    k_finnl<<<(BQ*32+255)/256, 256>>>(outB, outA, 8);
    // 8. layer 4: 32 -> 1 (dedicated GEMV, no padded-GEMM waste)
    k_bin<64,3136><<<BQ, 128>>>(feats);
    k_gemv2<<<BQ/8, 256>>>(X, KS+OFFL4, 3136);
    // 9. apply correction
    k_final<<<(BQ+127)/128, 128>>>(p0, dout, half);
}

// round 3
// speedup vs baseline: 1.7997x; 1.1337x over previous
#include <cuda_runtime.h>
#include <math.h>

#define BB 4
#define NN 512
#define BQ 2048
#define KBINS 48
#define PI_F 3.14159265358979f
#define NSPLIT 18

typedef unsigned long long ull;

// ---------------- device scratch ----------------
__device__ __align__(16) float g_X[BQ * 4704];
__device__ __align__(16) float g_Xo[BQ * 96];
__device__ __align__(16) uint2 g_list [BQ * NN];
__device__ int   g_cnt [BQ];
__device__ __align__(16) uint2 g_listo[BQ * NN];
__device__ int   g_cnto[BQ];
__device__ __align__(16) float g_KS[838784];
__device__ __align__(16) float g_part[NSPLIT * BQ * 64];
__device__ __align__(16) float g_outA[BQ * 96];
__device__ __align__(16) float g_outB[BQ * 96];
__device__ __align__(16) float g_feats[BQ * 96];
__device__ float g_p1[BQ * 2];
__device__ float g_out4[BQ * 2];

// KS segment offsets (floats) — contiguous, so offsets are also prefix sums
#define OFF1A 0        // rows 1984, cols 64
#define OFF1B 126976   // rows 96,   cols 32
#define OFFL1 130048   // rows 4704, cols 64
#define OFFL2 431104   // rows 3136, cols 64
#define OFFL3 631808   // rows 3136, cols 64
#define OFFL4 832512   // rows 3136, cols 2
#define KS_TOTAL 838784

// ---------------- packed f32x2 helpers ----------------
__device__ __forceinline__ void fma2(ull &d, ull a, ull b) {
    asm("fma.rn.f32x2 %0, %1, %2, %0;" : "+l"(d) : "l"(a), "l"(b));
}
__device__ __forceinline__ ull dup2(float a) {
    ull r;
    asm("mov.b64 %0, {%1, %1};" : "=l"(r) : "r"(__float_as_uint(a)));
    return r;
}

// ---------------- kernels ----------------

__global__ void k_prep(const float* __restrict__ p0, const float* __restrict__ v0,
                       const float* __restrict__ a, const float* __restrict__ other,
                       const float* __restrict__ v0enc)
{
    int i = blockIdx.x*blockDim.x + threadIdx.x;
    if (i >= BQ) return;
    float v0x = v0[i*2], v0y = v0[i*2+1];
    float v1x = v0x + 0.1f*a[i*2], v1y = v0y + 0.1f*a[i*2+1];
    g_p1[i*2]   = p0[i*2]   + 0.05f*(v0x+v1x);
    g_p1[i*2+1] = p0[i*2+1] + 0.05f*(v0y+v1y);
    float* f = g_feats + i*40;
    f[0]=v1x; f[1]=v1y;
    #pragma unroll
    for (int c=0;c<3;c++){ f[2+c*2]=other[(i*3+c)*2]; f[3+c*2]=other[(i*3+c)*2+1]; }
    #pragma unroll
    for (int c=0;c<16;c++){ f[8+c*2]=v0enc[(i*16+c)*2]; f[9+c*2]=v0enc[(i*16+c)*2+1]; }
}

// fused geometry + compaction: one warp per query row, deterministic order by s
__global__ void k_compact(const float* __restrict__ src, const float* __restrict__ qry,
                          const float* __restrict__ mask,
                          uint2* __restrict__ list, int* __restrict__ cnt)
{
    int warp = (blockIdx.x*blockDim.x + threadIdx.x) >> 5;
    int lane = threadIdx.x & 31;
    if (warp >= BQ) return;
    int b = warp >> 9, q = warp & 511;
    float qx = qry[(b*NN+q)*2], qy = qry[(b*NN+q)*2+1];
    const float* mrow = mask + (size_t)warp*NN;
    uint2* lrow = list + (size_t)warp*NN;
    int base = 0;
    for (int c = 0; c < NN; c += 32) {
        int s = c + lane;
        float rx = src[(b*NN+s)*2]   - qx;
        float ry = src[(b*NN+s)*2+1] - qy;
        float d2 = rx*rx + ry*ry;
        float m = mrow[s];
        float win = 1.0f - d2*(1.0f/1600.0f);
        bool on = (win > 0.f) && (m != 0.f);
        float wv = 0.f; int kidx = 0;
        if (on) {
            wv = win*win*win*m;
            float dist = sqrtf(d2 + 1e-9f);
            int rb = (int)(dist*(3.0f/40.0f)); if (rb > 2) rb = 2;
            int tb = ((int)floorf((atan2f(ry,rx) + PI_F)*(16.0f/(2.0f*PI_F)))) & 15;
            kidx = rb*16 + tb;
        }
        unsigned mk = __ballot_sync(0xffffffffu, on);
        if (on) {
            int pos = base + __popc(mk & ((1u<<lane)-1u));
            lrow[pos] = make_uint2(__float_as_uint(wv), (unsigned)((kidx<<16) | s));
        }
        base += __popc(mk);
    }
    if (lane == 0) cnt[warp] = base;
}

// single-launch steered-kernel matrix assembly, flat-indexed over all 6 segments
struct SteerArgs { const float* Wc[6]; const float* Ad[6]; const float* Bd[6]; };
__device__ const int c_pref[7] = {OFF1A, OFF1B, OFFL1, OFFL2, OFFL3, OFFL4, KS_TOTAL};
__device__ const int c_O[6]    = {16, 16, 32, 32, 32, 1};
__device__ const int c_I[6]    = {20, 1, 48, 32, 32, 32};
__device__ const int c_cols[6] = {64, 32, 64, 64, 64, 2};
__device__ const int c_dOff[6] = {32, -1, 0, 0, 0, 0};

__global__ void k_steer_all(SteerArgs args)
{
    int gidx = blockIdx.x*blockDim.x + threadIdx.x;
    if (gidx >= KS_TOTAL) return;
    int seg = 0;
    #pragma unroll
    for (int t = 1; t < 6; ++t) if (gidx >= c_pref[t]) seg = t;
    int idx = gidx - c_pref[seg];
    int cols = c_cols[seg];
    int row = idx / cols, col = idx % cols;
    int O = c_O[seg], I = c_I[seg], IV = 2*I;
    float val = 0.f;
    if (row < KBINS*IV) {
        if (col < 2*O) {
            int k = row / IV, iv = row % IV, i = iv>>1, v = iv&1;
            int o = col>>1, u = col&1;
            int t = k & 15;
            float th = (t + 0.5f)*(2.0f*PI_F/16.0f) - PI_F;
            float c = cosf(th), s = sinf(th);
            float R[2][2] = {{c,-s},{s,c}};
            const float* Wb = args.Wc[seg] + (((long long)k*O + o)*I + i)*4;
            val = R[u][0]*(Wb[0]*R[v][0] + Wb[1]*R[v][1])
                + R[u][1]*(Wb[2]*R[v][0] + Wb[3]*R[v][1]);
        }
    } else if (row < KBINS*IV + IV) {
        int dOff = c_dOff[seg];
        if (dOff >= 0 && col >= dOff && col < dOff + 2*O) {
            int iv = row - KBINS*IV, i = iv>>1, v = iv&1;
            int oc = col - dOff, o = oc>>1, u = oc&1;
            if (u == v) val = args.Ad[seg][o*I+i];
            else        val = (u==0) ? -args.Bd[seg][o*I+i] : args.Bd[seg][o*I+i];
        }
    }
    g_KS[gidx] = val;
}

// fluid binning over compacted list, float2 lanes
template<int IV, int LD>
__global__ void k_bin(const float* __restrict__ feats)
{
    __shared__ float sM[KBINS*IV];
    __shared__ uint2 sl[NN];
    int bq = blockIdx.x, tid = threadIdx.x, b = bq >> 9;
    int cnt = g_cnt[bq];
    const uint2* lrow = g_list + (size_t)bq*NN;
    for (int i = tid; i < cnt; i += blockDim.x) sl[i] = lrow[i];
    for (int i = tid; i < KBINS*IV; i += blockDim.x) sM[i] = 0.f;
    __syncthreads();
    const int HV = IV/2;
    if (tid < HV) {
        const float2* fb = (const float2*)feats + (size_t)(b*NN)*HV + tid;
        float2* sm2 = (float2*)sM;
        for (int e = 0; e < cnt; ++e) {
            uint2 pk = sl[e];
            float ws = __uint_as_float(pk.x);
            int s = pk.y & 0xffff, k = pk.y >> 16;
            float2 f = fb[(size_t)s*HV];
            float2 acc = sm2[k*HV + tid];
            acc.x += ws*f.x; acc.y += ws*f.y;
            sm2[k*HV + tid] = acc;
        }
    }
    __syncthreads();
    float* xr = g_X + (size_t)bq*LD;
    for (int i = tid; i < KBINS*IV; i += blockDim.x) xr[i] = sM[i];
    for (int i = tid; i < IV; i += blockDim.x)
        xr[KBINS*IV + i] = feats[(size_t)bq*IV + i];
    for (int i = 49*IV + tid; i < LD; i += blockDim.x) xr[i] = 0.f;
}

// obstacle binning (I=1): thread owns (k,v) slot, scans compacted list
__global__ void k_bino(const float* __restrict__ box_feats)
{
    __shared__ uint2 sl[NN];
    __shared__ float sbf[NN*2];
    int bq = blockIdx.x, tid = threadIdx.x, b = bq >> 9;
    int cnt = g_cnto[bq];
    const uint2* lrow = g_listo + (size_t)bq*NN;
    for (int i = tid; i < cnt; i += blockDim.x) sl[i] = lrow[i];
    for (int i = tid; i < NN*2; i += blockDim.x) sbf[i] = box_feats[b*NN*2 + i];
    __syncthreads();
    if (tid < 96) {
        int k = tid >> 1, v = tid & 1;
        float acc = 0.f;
        for (int e = 0; e < cnt; ++e) {
            uint2 pk = sl[e];
            if ((int)(pk.y >> 16) == k)
                acc += __uint_as_float(pk.x) * sbf[(pk.y & 0xffff)*2 + v];
        }
        g_Xo[bq*96 + tid] = acc;
    }
}

// main GEMM: [2048, inner] x [inner, 64] -> split-K partials.
// BM=128, BN=64, BK=16, 128 threads, 8x8 per-thread tile, f32x2 packed FMA.
#define GBM 128
#define GBN 64
#define GBK 16
__global__ void k_gemm2(const float* __restrict__ X, const float* __restrict__ Wm,
                        int inner)
{
    __shared__ float Xs[GBK][GBM+4];
    __shared__ float Ws[GBK][GBN];
    int ntiles = inner / GBK;
    int per = (ntiles + NSPLIT - 1) / NSPLIT;
    int t0 = blockIdx.y * per;
    int t1 = min(ntiles, t0 + per);
    int row0 = blockIdx.x * GBM;
    int tid = threadIdx.x;            // 128
    int tx = tid & 7, ty = tid >> 3;  // 8 col-groups x 16 row-groups, 8x8 each
    ull acc[8][4];
    #pragma unroll
    for (int i = 0; i < 8; ++i)
        #pragma unroll
        for (int j = 0; j < 4; ++j) acc[i][j] = 0ull;

    int xr0 = tid >> 2;        // 0..31
    int xc  = (tid & 3) * 4;   // k-chunk offset
    int wk  = tid >> 3;        // 0..15
    int wc  = (tid & 7) * 8;   // col offset (two float4 per thread)

    for (int t = t0; t < t1; ++t) {
        int kk = t*GBK;
        #pragma unroll
        for (int r = 0; r < 4; ++r) {
            int m = xr0 + r*32;
            float4 v = *(const float4*)&X[(size_t)(row0 + m)*inner + kk + xc];
            Xs[xc+0][m] = v.x; Xs[xc+1][m] = v.y; Xs[xc+2][m] = v.z; Xs[xc+3][m] = v.w;
        }
        {
            float4 v0 = *(const float4*)&Wm[(size_t)(kk+wk)*GBN + wc];
            float4 v1 = *(const float4*)&Wm[(size_t)(kk+wk)*GBN + wc + 4];
            *(float4*)&Ws[wk][wc]   = v0;
            *(float4*)&Ws[wk][wc+4] = v1;
        }
        __syncthreads();
        #pragma unroll
        for (int k = 0; k < GBK; ++k) {
            float4 a0 = *(const float4*)&Xs[k][ty*8];
            float4 a1 = *(const float4*)&Xs[k][ty*8+4];
            ulonglong2 bl = *(const ulonglong2*)&Ws[k][tx*8];
            ulonglong2 bh = *(const ulonglong2*)&Ws[k][tx*8+4];
            ull b[4] = {bl.x, bl.y, bh.x, bh.y};
            float av[8] = {a0.x,a0.y,a0.z,a0.w,a1.x,a1.y,a1.z,a1.w};
            #pragma unroll
            for (int i = 0; i < 8; ++i) {
                ull ad = dup2(av[i]);
                fma2(acc[i][0], ad, b[0]);
                fma2(acc[i][1], ad, b[1]);
                fma2(acc[i][2], ad, b[2]);
                fma2(acc[i][3], ad, b[3]);
            }
        }
        __syncthreads();
    }
    #pragma unroll
    for (int i = 0; i < 8; ++i) {
        ull* p = (ull*)(g_part + ((size_t)blockIdx.y*BQ + row0 + ty*8 + i)*64 + tx*8);
        ulonglong2 v0; v0.x = acc[i][0]; v0.y = acc[i][1];
        ulonglong2 v1; v1.x = acc[i][2]; v1.y = acc[i][3];
        *(ulonglong2*)p = v0;
        *(ulonglong2*)(p+2) = v1;
    }
}

// small GEMM for obstacle conv: [2048, 96] x [96, 32]
#define BM 32
#define BK 32
__global__ void k_gemms(const float* __restrict__ X, const float* __restrict__ Wm,
                        int inner, int cols)
{
    int row0 = blockIdx.x * BM;
    __shared__ float Xs[BK][BM];
    __shared__ float Ws[BK][64];
    int tid = threadIdx.x;
    int tx = tid & 15, ty = tid >> 4;
    float acc[4][4] = {};
    for (int kk = 0; kk < inner; kk += BK) {
        {
            int m  = tid >> 3;
            int kq = (tid & 7)*4;
            #pragma unroll
            for (int r = 0; r < 2; ++r) {
                float4 v = *(const float4*)&X[(size_t)(row0 + m + r*16)*inner + kk + kq];
                Xs[kq+0][m+r*16] = v.x; Xs[kq+1][m+r*16] = v.y;
                Xs[kq+2][m+r*16] = v.z; Xs[kq+3][m+r*16] = v.w;
            }
        }
        {
            int k = tid >> 4;
            int c = (tid & 15)*4;
            #pragma unroll
            for (int r = 0; r < 4; ++r) {
                int kr = k + r*8;
                float4 v = (c < cols) ? *(const float4*)&Wm[(size_t)(kk+kr)*cols + c]
                                      : make_float4(0.f,0.f,0.f,0.f);
                *(float4*)&Ws[kr][c] = v;
            }
        }
        __syncthreads();
        #pragma unroll
        for (int k = 0; k < BK; ++k) {
            float4 av = *(const float4*)&Xs[k][ty*4];
            float4 bv = *(const float4*)&Ws[k][tx*4];
            acc[0][0] += av.x*bv.x; acc[0][1] += av.x*bv.y; acc[0][2] += av.x*bv.z; acc[0][3] += av.x*bv.w;
            acc[1][0] += av.y*bv.x; acc[1][1] += av.y*bv.y; acc[1][2] += av.y*bv.z; acc[1][3] += av.y*bv.w;
            acc[2][0] += av.z*bv.x; acc[2][1] += av.z*bv.y; acc[2][2] += av.z*bv.z; acc[2][3] += av.z*bv.w;
            acc[3][0] += av.w*bv.x; acc[3][1] += av.w*bv.y; acc[3][2] += av.w*bv.z; acc[3][3] += av.w*bv.w;
        }
        __syncthreads();
    }
    float* p = g_part + (size_t)row0*64;
    #pragma unroll
    for (int i = 0; i < 4; ++i) {
        float4 v = make_float4(acc[i][0], acc[i][1], acc[i][2], acc[i][3]);
        *(float4*)&p[(ty*4+i)*64 + tx*4] = v;
    }
}

// layer 4: cols=2 GEMV, one warp per output row, W in smem, shfl reduce
__global__ void k_gemv2(const float* __restrict__ X, const float* __restrict__ Wm, int inner)
{
    __shared__ float Wsh[3136*2];
    int tid = threadIdx.x;
    for (int i = tid; i < inner*2; i += blockDim.x) Wsh[i] = Wm[i];
    __syncthreads();
    int warp = tid >> 5, lane = tid & 31;
    int row = blockIdx.x*8 + warp;
    const float* xr = X + (size_t)row*inner;
    float a0 = 0.f, a1 = 0.f;
    for (int k = lane; k < inner; k += 32) {
        float x = xr[k];
        a0 += x*Wsh[k*2];
        a1 += x*Wsh[k*2+1];
    }
    #pragma unroll
    for (int o = 16; o; o >>= 1) {
        a0 += __shfl_down_sync(0xffffffffu, a0, o);
        a1 += __shfl_down_sync(0xffffffffu, a1, o);
    }
    if (lane == 0) { g_out4[row*2] = a0; g_out4[row*2+1] = a1; }
}

// sum split-K partials into output buffer (stage 1)
__global__ void k_finish(float* __restrict__ out, int outLd, int colOff, int cols, int nsplit)
{
    int idx = blockIdx.x*blockDim.x + threadIdx.x;
    if (idx >= BQ*cols) return;
    int row = idx / cols, col = idx % cols;
    float v = 0.f;
    for (int s = 0; s < nsplit; ++s) v += g_part[((size_t)s*BQ + row)*64 + col];
    out[row*outLd + colOff + col] = v;
}

// fused: sum partials + residual + nonlinearity (64-col layers)
__global__ void k_finnl(float* __restrict__ out, const float* __restrict__ res, int nsplit)
{
    int idx = blockIdx.x*blockDim.x + threadIdx.x;
    if (idx >= BQ*32) return;
    int row = idx >> 5, c = idx & 31;
    float x = 0.f, y = 0.f;
    for (int s = 0; s < nsplit; ++s) {
        const float* p = g_part + ((size_t)s*BQ + row)*64 + c*2;
        x += p[0]; y += p[1];
    }
    if (res) { x += res[row*64 + c*2]; y += res[row*64 + c*2+1]; }
    out[row*64 + c*2] = x; out[row*64 + c*2+1] = y;
    float mag = x*x + y*y + 1e-6f;
    float sc = fmaxf(mag - 0.2f, 0.f) / mag;
    g_feats[row*64 + c*2]   = x*sc;
    g_feats[row*64 + c*2+1] = y*sc;
}

// stage-1 nonlinearity (48 ch, ld 96)
__global__ void k_nonlin(const float* __restrict__ out, int C)
{
    int idx = blockIdx.x*blockDim.x + threadIdx.x;
    if (idx >= BQ*C) return;
    float x = out[idx*2], y = out[idx*2+1];
    float mag = x*x + y*y + 1e-6f;
    float sc = fmaxf(mag - 0.2f, 0.f) / mag;
    g_feats[idx*2]   = x*sc;
    g_feats[idx*2+1] = y*sc;
}

__global__ void k_final(const float* __restrict__ p0, float* __restrict__ dout, int half)
{
    int i = blockIdx.x*blockDim.x + threadIdx.x;
    if (i >= BQ) return;
    float px = g_p1[i*2]   + g_out4[i*2]  *(1.0f/128.0f);
    float py = g_p1[i*2+1] + g_out4[i*2+1]*(1.0f/128.0f);
    dout[i*2]   = px;
    dout[i*2+1] = py;
    dout[half + i*2]   = (px - p0[i*2])  *10.0f;
    dout[half + i*2+1] = (py - p0[i*2+1])*10.0f;
}

// ---------------- host driver ----------------
extern "C" void kernel_launch(void* const* d_in, const int* in_sizes, int n_in,
                              void* d_out, int out_size)
{
    const float* v0_enc = (const float*)d_in[1];
    const float* p0     = (const float*)d_in[2];
    const float* v0     = (const float*)d_in[3];
    const float* a      = (const float*)d_in[4];
    const float* other  = (const float*)d_in[5];
    const float* box    = (const float*)d_in[6];
    const float* boxf   = (const float*)d_in[7];
    const float* fmask  = (const float*)d_in[8];
    const float* bmask  = (const float*)d_in[9];
    float* dout = (float*)d_out;
    int half = out_size / 2;

    float *X, *Xo, *KS, *outA, *outB, *feats, *p1;
    uint2 *list, *listo; int *cnt, *cnto;
    cudaGetSymbolAddress((void**)&X,     g_X);
    cudaGetSymbolAddress((void**)&Xo,    g_Xo);
    cudaGetSymbolAddress((void**)&KS,    g_KS);
    cudaGetSymbolAddress((void**)&outA,  g_outA);
    cudaGetSymbolAddress((void**)&outB,  g_outB);
    cudaGetSymbolAddress((void**)&feats, g_feats);
    cudaGetSymbolAddress((void**)&p1,    g_p1);
    cudaGetSymbolAddress((void**)&list,  g_list);
    cudaGetSymbolAddress((void**)&listo, g_listo);
    cudaGetSymbolAddress((void**)&cnt,   g_cnt);
    cudaGetSymbolAddress((void**)&cnto,  g_cnto);

    SteerArgs sa;
    sa.Wc[0] = (const float*)d_in[10]; sa.Ad[0] = (const float*)d_in[12]; sa.Bd[0] = (const float*)d_in[13];
    sa.Wc[1] = (const float*)d_in[11]; sa.Ad[1] = nullptr;                sa.Bd[1] = nullptr;
    sa.Wc[2] = (const float*)d_in[14]; sa.Ad[2] = (const float*)d_in[15]; sa.Bd[2] = (const float*)d_in[16];
    sa.Wc[3] = (const float*)d_in[17]; sa.Ad[3] = (const float*)d_in[18]; sa.Bd[3] = (const float*)d_in[19];
    sa.Wc[4] = (const float*)d_in[20]; sa.Ad[4] = (const float*)d_in[21]; sa.Bd[4] = (const float*)d_in[22];
    sa.Wc[5] = (const float*)d_in[23]; sa.Ad[5] = (const float*)d_in[24]; sa.Bd[5] = (const float*)d_in[25];

    dim3 gg(BQ/GBM, NSPLIT);  // 16 x 18 = 288 blocks

    // 1. integrate + build 20-ch fluid feats
    k_prep<<<(BQ+127)/128, 128>>>(p0, v0, a, other, v0_enc);
    // 2. fused geometry + compaction
    k_compact<<<BQ/8, 256>>>(p1, p1, fmask, list, cnt);
    k_compact<<<BQ/8, 256>>>(box, p1, bmask, listo, cnto);
    // 3. assemble all steered GEMM matrices (flat index)
    k_steer_all<<<(KS_TOTAL+255)/256, 256>>>(sa);
    // 4. stage 1: fluid conv + dense -> outA cols 32..95; obstacle -> cols 0..31
    k_bino<<<BQ, 128>>>(boxf);
    k_bin<40,1984><<<BQ, 128>>>(feats);
    k_gemm2<<<gg, 128>>>(X, KS+OFF1A, 1984);
    k_finish<<<(BQ*64+255)/256, 256>>>(outA, 96, 32, 64, NSPLIT);
    k_gemms<<<64, 128>>>(Xo, KS+OFF1B, 96, 32);
    k_finish<<<(BQ*32+255)/256, 256>>>(outA, 96, 0, 32, 1);
    k_nonlin<<<(BQ*48+255)/256, 256>>>(outA, 48);
    // 5. layer 1: 48 -> 32
    k_bin<96,4704><<<BQ, 128>>>(feats);
    k_gemm2<<<gg, 128>>>(X, KS+OFFL1, 4704);
    k_finnl<<<(BQ*32+255)/256, 256>>>(outB, nullptr, NSPLIT);
    // 6. layer 2: 32 -> 32, residual
    k_bin<64,3136><<<BQ, 128>>>(feats);
    k_gemm2<<<gg, 128>>>(X, KS+OFFL2, 3136);
    k_finnl<<<(BQ*32+255)/256, 256>>>(outA, outB, NSPLIT);
    // 7. layer 3: 32 -> 32, residual
    k_bin<64,3136><<<BQ, 128>>>(feats);
    k_gemm2<<<gg, 128>>>(X, KS+OFFL3, 3136);
    k_finnl<<<(BQ*32+255)/256, 256>>>(outB, outA, NSPLIT);
    // 8. layer 4: 32 -> 1 (dedicated GEMV)
    k_bin<64,3136><<<BQ, 128>>>(feats);
    k_gemv2<<<BQ/8, 256>>>(X, KS+OFFL4, 3136);
    // 9. apply correction
    k_final<<<(BQ+127)/128, 128>>>(p0, dout, half);
}

// round 5
// speedup vs baseline: 1.9014x; 1.0565x over previous
#include <cuda_runtime.h>
#include <math.h>
#include <stdint.h>

#define BB 4
#define NN 512
#define BQ 2048
#define KBINS 48
#define PI_F 3.14159265358979f
#define NSPLIT 8

typedef unsigned long long ull;

// ---------------- device scratch ----------------
__device__ __align__(16) float g_X[BQ * 4704];
__device__ __align__(16) float g_Xo[BQ * 96];
__device__ __align__(16) uint2 g_list [BQ * NN];
__device__ int   g_cnt [BQ];
__device__ __align__(16) uint2 g_listo[BQ * NN];
__device__ int   g_cnto[BQ];
__device__ __align__(16) float g_KS[838784];
__device__ __align__(16) float g_part[NSPLIT * BQ * 64];
__device__ __align__(16) float g_outA[BQ * 96];
__device__ __align__(16) float g_outB[BQ * 96];
__device__ __align__(16) float g_feats[BQ * 96];
__device__ float g_p1[BQ * 2];
__device__ float g_out4[BQ * 2];

// KS segment offsets (floats) — contiguous prefix sums
#define OFF1A 0        // TC: 64 x 1984 (transposed, ld=1984)
#define OFF1B 126976   // row-major 96 x 32 (obstacle)
#define OFFL1 130048   // TC: 64 x 4704
#define OFFL2 431104   // TC: 64 x 3136
#define OFFL3 631808   // TC: 64 x 3136
#define OFFL4 832512   // row-major 3136 x 2 (gemv)
#define KS_TOTAL 838784

// ---------------- helpers ----------------
__device__ __forceinline__ float tf32r(float x) {
    uint32_t r; asm("cvt.rna.tf32.f32 %0, %1;" : "=r"(r) : "f"(x));
    return __uint_as_float(r);
}

// ---------------- kernels ----------------

__global__ void k_prep(const float* __restrict__ p0, const float* __restrict__ v0,
                       const float* __restrict__ a, const float* __restrict__ other,
                       const float* __restrict__ v0enc)
{
    int i = blockIdx.x*blockDim.x + threadIdx.x;
    if (i >= BQ) return;
    float v0x = v0[i*2], v0y = v0[i*2+1];
    float v1x = v0x + 0.1f*a[i*2], v1y = v0y + 0.1f*a[i*2+1];
    g_p1[i*2]   = p0[i*2]   + 0.05f*(v0x+v1x);
    g_p1[i*2+1] = p0[i*2+1] + 0.05f*(v0y+v1y);
    float* f = g_feats + i*40;
    f[0]=v1x; f[1]=v1y;
    #pragma unroll
    for (int c=0;c<3;c++){ f[2+c*2]=other[(i*3+c)*2]; f[3+c*2]=other[(i*3+c)*2+1]; }
    #pragma unroll
    for (int c=0;c<16;c++){ f[8+c*2]=v0enc[(i*16+c)*2]; f[9+c*2]=v0enc[(i*16+c)*2+1]; }
}

__global__ void k_compact(const float* __restrict__ src, const float* __restrict__ qry,
                          const float* __restrict__ mask,
                          uint2* __restrict__ list, int* __restrict__ cnt)
{
    int warp = (blockIdx.x*blockDim.x + threadIdx.x) >> 5;
    int lane = threadIdx.x & 31;
    if (warp >= BQ) return;
    int b = warp >> 9, q = warp & 511;
    float qx = qry[(b*NN+q)*2], qy = qry[(b*NN+q)*2+1];
    const float* mrow = mask + (size_t)warp*NN;
    uint2* lrow = list + (size_t)warp*NN;
    int base = 0;
    for (int c = 0; c < NN; c += 32) {
        int s = c + lane;
        float rx = src[(b*NN+s)*2]   - qx;
        float ry = src[(b*NN+s)*2+1] - qy;
        float d2 = rx*rx + ry*ry;
        float m = mrow[s];
        float win = 1.0f - d2*(1.0f/1600.0f);
        bool on = (win > 0.f) && (m != 0.f);
        float wv = 0.f; int kidx = 0;
        if (on) {
            wv = win*win*win*m;
            float dist = sqrtf(d2 + 1e-9f);
            int rb = (int)(dist*(3.0f/40.0f)); if (rb > 2) rb = 2;
            int tb = ((int)floorf((atan2f(ry,rx) + PI_F)*(16.0f/(2.0f*PI_F)))) & 15;
            kidx = rb*16 + tb;
        }
        unsigned mk = __ballot_sync(0xffffffffu, on);
        if (on) {
            int pos = base + __popc(mk & ((1u<<lane)-1u));
            lrow[pos] = make_uint2(__float_as_uint(wv), (unsigned)((kidx<<16) | s));
        }
        base += __popc(mk);
    }
    if (lane == 0) cnt[warp] = base;
}

// steered-kernel assembly. TC segments (0,2,3,4) stored TRANSPOSED [col][k], tf32-rounded.
struct SteerArgs { const float* Wc[6]; const float* Ad[6]; const float* Bd[6]; };
__device__ const int c_pref[7] = {OFF1A, OFF1B, OFFL1, OFFL2, OFFL3, OFFL4, KS_TOTAL};
__device__ const int c_O[6]    = {16, 16, 32, 32, 32, 1};
__device__ const int c_I[6]    = {20, 1, 48, 32, 32, 32};
__device__ const int c_cols[6] = {64, 32, 64, 64, 64, 2};
__device__ const int c_dOff[6] = {32, -1, 0, 0, 0, 0};
__device__ const int c_K[6]    = {1984, 96, 4704, 3136, 3136, 3136};
__device__ const int c_tc[6]   = {1, 0, 1, 1, 1, 0};

__global__ void k_steer_all(SteerArgs args)
{
    int gidx = blockIdx.x*blockDim.x + threadIdx.x;
    if (gidx >= KS_TOTAL) return;
    int seg = 0;
    #pragma unroll
    for (int t = 1; t < 6; ++t) if (gidx >= c_pref[t]) seg = t;
    int idx = gidx - c_pref[seg];
    int row, col;
    bool tc = c_tc[seg];
    if (tc) { int K = c_K[seg]; col = idx / K; row = idx % K; }
    else    { int cols = c_cols[seg]; row = idx / cols; col = idx % cols; }
    int O = c_O[seg], I = c_I[seg], IV = 2*I;
    float val = 0.f;
    if (row < KBINS*IV) {
        if (col < 2*O) {
            int k = row / IV, iv = row % IV, i = iv>>1, v = iv&1;
            int o = col>>1, u = col&1;
            int t = k & 15;
            float th = (t + 0.5f)*(2.0f*PI_F/16.0f) - PI_F;
            float c = cosf(th), s = sinf(th);
            float R[2][2] = {{c,-s},{s,c}};
            const float* Wb = args.Wc[seg] + (((long long)k*O + o)*I + i)*4;
            val = R[u][0]*(Wb[0]*R[v][0] + Wb[1]*R[v][1])
                + R[u][1]*(Wb[2]*R[v][0] + Wb[3]*R[v][1]);
        }
    } else if (row < KBINS*IV + IV) {
        int dOff = c_dOff[seg];
        if (dOff >= 0 && col >= dOff && col < dOff + 2*O) {
            int iv = row - KBINS*IV, i = iv>>1, v = iv&1;
            int oc = col - dOff, o = oc>>1, u = oc&1;
            if (u == v) val = args.Ad[seg][o*I+i];
            else        val = (u==0) ? -args.Bd[seg][o*I+i] : args.Bd[seg][o*I+i];
        }
    }
    g_KS[gidx] = tc ? tf32r(val) : val;
}

// fluid binning over compacted list; RND -> tf32-round outputs for TC consumer
template<int IV, int LD, bool RND>
__global__ void k_bin(const float* __restrict__ feats)
{
    __shared__ float sM[KBINS*IV];
    __shared__ uint2 sl[NN];
    int bq = blockIdx.x, tid = threadIdx.x, b = bq >> 9;
    int cnt = g_cnt[bq];
    const uint2* lrow = g_list + (size_t)bq*NN;
    for (int i = tid; i < cnt; i += blockDim.x) sl[i] = lrow[i];
    for (int i = tid; i < KBINS*IV; i += blockDim.x) sM[i] = 0.f;
    __syncthreads();
    const int HV = IV/2;
    if (tid < HV) {
        const float2* fb = (const float2*)feats + (size_t)(b*NN)*HV + tid;
        float2* sm2 = (float2*)sM;
        for (int e = 0; e < cnt; ++e) {
            uint2 pk = sl[e];
            float ws = __uint_as_float(pk.x);
            int s = pk.y & 0xffff, k = pk.y >> 16;
            float2 f = fb[(size_t)s*HV];
            float2 acc = sm2[k*HV + tid];
            acc.x += ws*f.x; acc.y += ws*f.y;
            sm2[k*HV + tid] = acc;
        }
    }
    __syncthreads();
    float* xr = g_X + (size_t)bq*LD;
    for (int i = tid; i < KBINS*IV; i += blockDim.x)
        xr[i] = RND ? tf32r(sM[i]) : sM[i];
    for (int i = tid; i < IV; i += blockDim.x) {
        float v = feats[(size_t)bq*IV + i];
        xr[KBINS*IV + i] = RND ? tf32r(v) : v;
    }
    for (int i = 49*IV + tid; i < LD; i += blockDim.x) xr[i] = 0.f;
}

__global__ void k_bino(const float* __restrict__ box_feats)
{
    __shared__ uint2 sl[NN];
    __shared__ float sbf[NN*2];
    int bq = blockIdx.x, tid = threadIdx.x, b = bq >> 9;
    int cnt = g_cnto[bq];
    const uint2* lrow = g_listo + (size_t)bq*NN;
    for (int i = tid; i < cnt; i += blockDim.x) sl[i] = lrow[i];
    for (int i = tid; i < NN*2; i += blockDim.x) sbf[i] = box_feats[b*NN*2 + i];
    __syncthreads();
    if (tid < 96) {
        int k = tid >> 1, v = tid & 1;
        float acc = 0.f;
        for (int e = 0; e < cnt; ++e) {
            uint2 pk = sl[e];
            if ((int)(pk.y >> 16) == k)
                acc += __uint_as_float(pk.x) * sbf[(pk.y & 0xffff)*2 + v];
        }
        g_Xo[bq*96 + tid] = acc;
    }
}

// ---------- tensor-core GEMM via mma.sync tf32 ----------
// [2048 x K] x [K x 64]; A = g_X (K-major), B = KS transposed [64][K] (K-major = mma col layout).
// Block: 128 thr (4 warps), BM=128, BN=64, BK=32. Warp tile 32x64 = 2 m-tiles x 8 n-tiles.
__global__ void k_gemm_mma(const float* __restrict__ X, const float* __restrict__ Wt, int inner)
{
    __shared__ float As[128][36];   // ld 36: frag bank = (4g+q)%32, conflict-free
    __shared__ float Bs[64][36];
    int tid = threadIdx.x, lane = tid & 31, warp = tid >> 5;
    int row0 = blockIdx.x * 128;
    int ntiles = inner / 32;
    int per = (ntiles + NSPLIT - 1) / NSPLIT;
    int t0 = blockIdx.y * per;
    int t1 = min(ntiles, t0 + per);
    int g = lane >> 2, q = lane & 3;

    float acc[2][8][4];
    #pragma unroll
    for (int a = 0; a < 2; ++a)
        #pragma unroll
        for (int b = 0; b < 8; ++b)
            #pragma unroll
            for (int c = 0; c < 4; ++c) acc[a][b][c] = 0.f;

    for (int t = t0; t < t1; ++t) {
        int kk = t*32;
        #pragma unroll
        for (int r = 0; r < 8; ++r) {          // A: 128 rows x 8 float4
            int idx = tid + r*128;
            int m = idx >> 3, c4 = (idx & 7)*4;
            float4 v = *(const float4*)&X[(size_t)(row0+m)*inner + kk + c4];
            *(float4*)&As[m][c4] = v;
        }
        #pragma unroll
        for (int r = 0; r < 4; ++r) {          // B: 64 rows x 8 float4
            int idx = tid + r*128;
            int n = idx >> 3, c4 = (idx & 7)*4;
            float4 v = *(const float4*)&Wt[(size_t)n*inner + kk + c4];
            *(float4*)&Bs[n][c4] = v;
        }
        __syncthreads();
        #pragma unroll
        for (int k8 = 0; k8 < 4; ++k8) {
            int kb = k8*8;
            uint32_t bf0[8], bf1[8];
            #pragma unroll
            for (int nt = 0; nt < 8; ++nt) {
                bf0[nt] = __float_as_uint(Bs[nt*8 + g][kb + q]);
                bf1[nt] = __float_as_uint(Bs[nt*8 + g][kb + q + 4]);
            }
            #pragma unroll
            for (int mt = 0; mt < 2; ++mt) {
                int mr = warp*32 + mt*16 + g;
                uint32_t a0 = __float_as_uint(As[mr][kb+q]);
                uint32_t a1 = __float_as_uint(As[mr+8][kb+q]);
                uint32_t a2 = __float_as_uint(As[mr][kb+q+4]);
                uint32_t a3 = __float_as_uint(As[mr+8][kb+q+4]);
                #pragma unroll
                for (int nt = 0; nt < 8; ++nt) {
                    asm volatile(
                        "mma.sync.aligned.m16n8k8.row.col.f32.tf32.tf32.f32 "
                        "{%0,%1,%2,%3}, {%4,%5,%6,%7}, {%8,%9}, {%0,%1,%2,%3};"
                        : "+f"(acc[mt][nt][0]), "+f"(acc[mt][nt][1]),
                          "+f"(acc[mt][nt][2]), "+f"(acc[mt][nt][3])
                        : "r"(a0), "r"(a1), "r"(a2), "r"(a3),
                          "r"(bf0[nt]), "r"(bf1[nt]));
                }
            }
        }
        __syncthreads();
    }
    float* pb = g_part + ((size_t)blockIdx.y*BQ + row0)*64;
    #pragma unroll
    for (int mt = 0; mt < 2; ++mt) {
        int r0 = warp*32 + mt*16 + g;
        #pragma unroll
        for (int nt = 0; nt < 8; ++nt) {
            int c = nt*8 + q*2;
            *(float2*)&pb[(size_t)r0*64 + c]     = make_float2(acc[mt][nt][0], acc[mt][nt][1]);
            *(float2*)&pb[(size_t)(r0+8)*64 + c] = make_float2(acc[mt][nt][2], acc[mt][nt][3]);
        }
    }
}

// small GEMM for obstacle conv: [2048, 96] x [96, 32] (fp32, row-major W)
#define BM 32
#define BK 32
__global__ void k_gemms(const float* __restrict__ X, const float* __restrict__ Wm,
                        int inner, int cols)
{
    int row0 = blockIdx.x * BM;
    __shared__ float Xs[BK][BM];
    __shared__ float Ws[BK][64];
    int tid = threadIdx.x;
    int tx = tid & 15, ty = tid >> 4;
    float acc[4][4] = {};
    for (int kk = 0; kk < inner; kk += BK) {
        {
            int m  = tid >> 3;
            int kq = (tid & 7)*4;
            #pragma unroll
            for (int r = 0; r < 2; ++r) {
                float4 v = *(const float4*)&X[(size_t)(row0 + m + r*16)*inner + kk + kq];
                Xs[kq+0][m+r*16] = v.x; Xs[kq+1][m+r*16] = v.y;
                Xs[kq+2][m+r*16] = v.z; Xs[kq+3][m+r*16] = v.w;
            }
        }
        {
            int k = tid >> 4;
            int c = (tid & 15)*4;
            #pragma unroll
            for (int r = 0; r < 4; ++r) {
                int kr = k + r*8;
                float4 v = (c < cols) ? *(const float4*)&Wm[(size_t)(kk+kr)*cols + c]
                                      : make_float4(0.f,0.f,0.f,0.f);
                *(float4*)&Ws[kr][c] = v;
            }
        }
        __syncthreads();
        #pragma unroll
        for (int k = 0; k < BK; ++k) {
            float4 av = *(const float4*)&Xs[k][ty*4];
            float4 bv = *(const float4*)&Ws[k][tx*4];
            acc[0][0] += av.x*bv.x; acc[0][1] += av.x*bv.y; acc[0][2] += av.x*bv.z; acc[0][3] += av.x*bv.w;
            acc[1][0] += av.y*bv.x; acc[1][1] += av.y*bv.y; acc[1][2] += av.y*bv.z; acc[1][3] += av.y*bv.w;
            acc[2][0] += av.z*bv.x; acc[2][1] += av.z*bv.y; acc[2][2] += av.z*bv.z; acc[2][3] += av.z*bv.w;
            acc[3][0] += av.w*bv.x; acc[3][1] += av.w*bv.y; acc[3][2] += av.w*bv.z; acc[3][3] += av.w*bv.w;
        }
        __syncthreads();
    }
    float* p = g_part + (size_t)row0*64;
    #pragma unroll
    for (int i = 0; i < 4; ++i) {
        float4 v = make_float4(acc[i][0], acc[i][1], acc[i][2], acc[i][3]);
        *(float4*)&p[(ty*4+i)*64 + tx*4] = v;
    }
}

// layer 4: cols=2 GEMV
__global__ void k_gemv2(const float* __restrict__ X, const float* __restrict__ Wm, int inner)
{
    __shared__ float Wsh[3136*2];
    int tid = threadIdx.x;
    for (int i = tid; i < inner*2; i += blockDim.x) Wsh[i] = Wm[i];
    __syncthreads();
    int warp = tid >> 5, lane = tid & 31;
    int row = blockIdx.x*8 + warp;
    const float* xr = X + (size_t)row*inner;
    float a0 = 0.f, a1 = 0.f;
    for (int k = lane; k < inner; k += 32) {
        float x = xr[k];
        a0 += x*Wsh[k*2];
        a1 += x*Wsh[k*2+1];
    }
    #pragma unroll
    for (int o = 16; o; o >>= 1) {
        a0 += __shfl_down_sync(0xffffffffu, a0, o);
        a1 += __shfl_down_sync(0xffffffffu, a1, o);
    }
    if (lane == 0) { g_out4[row*2] = a0; g_out4[row*2+1] = a1; }
}

__global__ void k_finish(float* __restrict__ out, int outLd, int colOff, int cols, int nsplit)
{
    int idx = blockIdx.x*blockDim.x + threadIdx.x;
    if (idx >= BQ*cols) return;
    int row = idx / cols, col = idx % cols;
    float v = 0.f;
    for (int s = 0; s < nsplit; ++s) v += g_part[((size_t)s*BQ + row)*64 + col];
    out[row*outLd + colOff + col] = v;
}

__global__ void k_finnl(float* __restrict__ out, const float* __restrict__ res, int nsplit)
{
    int idx = blockIdx.x*blockDim.x + threadIdx.x;
    if (idx >= BQ*32) return;
    int row = idx >> 5, c = idx & 31;
    float x = 0.f, y = 0.f;
    for (int s = 0; s < nsplit; ++s) {
        const float* p = g_part + ((size_t)s*BQ + row)*64 + c*2;
        x += p[0]; y += p[1];
    }
    if (res) { x += res[row*64 + c*2]; y += res[row*64 + c*2+1]; }
    out[row*64 + c*2] = x; out[row*64 + c*2+1] = y;
    float mag = x*x + y*y + 1e-6f;
    float sc = fmaxf(mag - 0.2f, 0.f) / mag;
    g_feats[row*64 + c*2]   = x*sc;
    g_feats[row*64 + c*2+1] = y*sc;
}

__global__ void k_nonlin(const float* __restrict__ out, int C)
{
    int idx = blockIdx.x*blockDim.x + threadIdx.x;
    if (idx >= BQ*C) return;
    float x = out[idx*2], y = out[idx*2+1];
    float mag = x*x + y*y + 1e-6f;
    float sc = fmaxf(mag - 0.2f, 0.f) / mag;
    g_feats[idx*2]   = x*sc;
    g_feats[idx*2+1] = y*sc;
}

__global__ void k_final(const float* __restrict__ p0, float* __restrict__ dout, int half)
{
    int i = blockIdx.x*blockDim.x + threadIdx.x;
    if (i >= BQ) return;
    float px = g_p1[i*2]   + g_out4[i*2]  *(1.0f/128.0f);
    float py = g_p1[i*2+1] + g_out4[i*2+1]*(1.0f/128.0f);
    dout[i*2]   = px;
    dout[i*2+1] = py;
    dout[half + i*2]   = (px - p0[i*2])  *10.0f;
    dout[half + i*2+1] = (py - p0[i*2+1])*10.0f;
}

// ---------------- host driver ----------------
extern "C" void kernel_launch(void* const* d_in, const int* in_sizes, int n_in,
                              void* d_out, int out_size)
{
    const float* v0_enc = (const float*)d_in[1];
    const float* p0     = (const float*)d_in[2];
    const float* v0     = (const float*)d_in[3];
    const float* a      = (const float*)d_in[4];
    const float* other  = (const float*)d_in[5];
    const float* box    = (const float*)d_in[6];
    const float* boxf   = (const float*)d_in[7];
    const float* fmask  = (const float*)d_in[8];
    const float* bmask  = (const float*)d_in[9];
    float* dout = (float*)d_out;
    int half = out_size / 2;

    float *X, *Xo, *KS, *outA, *outB, *feats, *p1;
    uint2 *list, *listo; int *cnt, *cnto;
    cudaGetSymbolAddress((void**)&X,     g_X);
    cudaGetSymbolAddress((void**)&Xo,    g_Xo);
    cudaGetSymbolAddress((void**)&KS,    g_KS);
    cudaGetSymbolAddress((void**)&outA,  g_outA);
    cudaGetSymbolAddress((void**)&outB,  g_outB);
    cudaGetSymbolAddress((void**)&feats, g_feats);
    cudaGetSymbolAddress((void**)&p1,    g_p1);
    cudaGetSymbolAddress((void**)&list,  g_list);
    cudaGetSymbolAddress((void**)&listo, g_listo);
    cudaGetSymbolAddress((void**)&cnt,   g_cnt);
    cudaGetSymbolAddress((void**)&cnto,  g_cnto);

    SteerArgs sa;
    sa.Wc[0] = (const float*)d_in[10]; sa.Ad[0] = (const float*)d_in[12]; sa.Bd[0] = (const float*)d_in[13];
    sa.Wc[1] = (const float*)d_in[11]; sa.Ad[1] = nullptr;                sa.Bd[1] = nullptr;
    sa.Wc[2] = (const float*)d_in[14]; sa.Ad[2] = (const float*)d_in[15]; sa.Bd[2] = (const float*)d_in[16];
    sa.Wc[3] = (const float*)d_in[17]; sa.Ad[3] = (const float*)d_in[18]; sa.Bd[3] = (const float*)d_in[19];
    sa.Wc[4] = (const float*)d_in[20]; sa.Ad[4] = (const float*)d_in[21]; sa.Bd[4] = (const float*)d_in[22];
    sa.Wc[5] = (const float*)d_in[23]; sa.Ad[5] = (const float*)d_in[24]; sa.Bd[5] = (const float*)d_in[25];

    dim3 gg(BQ/128, NSPLIT);   // 16 x 8 = 128 CTAs

    // 1. integrate + build 20-ch fluid feats
    k_prep<<<(BQ+127)/128, 128>>>(p0, v0, a, other, v0_enc);
    // 2. fused geometry + compaction
    k_compact<<<BQ/8, 256>>>(p1, p1, fmask, list, cnt);
    k_compact<<<BQ/8, 256>>>(box, p1, bmask, listo, cnto);
    // 3. assemble all steered GEMM matrices (TC segments transposed + tf32-rounded)
    k_steer_all<<<(KS_TOTAL+255)/256, 256>>>(sa);
    // 4. stage 1
    k_bino<<<BQ, 128>>>(boxf);
    k_bin<40,1984,true><<<BQ, 128>>>(feats);
    k_gemm_mma<<<gg, 128>>>(X, KS+OFF1A, 1984);
    k_finish<<<(BQ*64+255)/256, 256>>>(outA, 96, 32, 64, NSPLIT);
    k_gemms<<<64, 128>>>(Xo, KS+OFF1B, 96, 32);
    k_finish<<<(BQ*32+255)/256, 256>>>(outA, 96, 0, 32, 1);
    k_nonlin<<<(BQ*48+255)/256, 256>>>(outA, 48);
    // 5. layer 1: 48 -> 32
    k_bin<96,4704,true><<<BQ, 128>>>(feats);
    k_gemm_mma<<<gg, 128>>>(X, KS+OFFL1, 4704);
    k_finnl<<<(BQ*32+255)/256, 256>>>(outB, nullptr, NSPLIT);
    // 6. layer 2: 32 -> 32, residual
    k_bin<64,3136,true><<<BQ, 128>>>(feats);
    k_gemm_mma<<<gg, 128>>>(X, KS+OFFL2, 3136);
    k_finnl<<<(BQ*32+255)/256, 256>>>(outA, outB, NSPLIT);
    // 7. layer 3: 32 -> 32, residual
    k_bin<64,3136,true><<<BQ, 128>>>(feats);
    k_gemm_mma<<<gg, 128>>>(X, KS+OFFL3, 3136);
    k_finnl<<<(BQ*32+255)/256, 256>>>(outB, outA, NSPLIT);
    // 8. layer 4: 32 -> 1 (GEMV, fp32)
    k_bin<64,3136,false><<<BQ, 128>>>(feats);
    k_gemv2<<<BQ/8, 256>>>(X, KS+OFFL4, 3136);
    // 9. apply correction
    k_final<<<(BQ+127)/128, 128>>>(p0, dout, half);
}

// round 6
// speedup vs baseline: 2.1224x; 1.1162x over previous
#include <cuda_runtime.h>
#include <math.h>
#include <stdint.h>

#define BB 4
#define NN 512
#define BQ 2048
#define KBINS 48
#define PI_F 3.14159265358979f
#define NSPLIT 8

typedef unsigned long long ull;

// ---------------- device scratch ----------------
__device__ __align__(16) float g_X[BQ * 4704];
__device__ __align__(16) float g_Xo[BQ * 96];
__device__ __align__(16) uint2 g_list [BQ * NN];
__device__ int   g_cnt [BQ];
__device__ __align__(16) uint2 g_listo[BQ * NN];
__device__ int   g_cnto[BQ];
__device__ __align__(16) float g_KS[838784];
__device__ __align__(16) float g_part[NSPLIT * BQ * 64];
__device__ __align__(16) float g_outA[BQ * 96];
__device__ __align__(16) float g_outB[BQ * 96];
__device__ __align__(16) float g_feats[BQ * 96];
__device__ float g_p1[BQ * 2];

// KS segment offsets (floats) — contiguous prefix sums
#define OFF1A 0        // TC: 64 x 1984 (transposed, ld=1984)
#define OFF1B 126976   // row-major 96 x 32 (obstacle)
#define OFFL1 130048   // TC: 64 x 4704
#define OFFL2 431104   // TC: 64 x 3136
#define OFFL3 631808   // TC: 64 x 3136
#define OFFL4 832512   // row-major 3136 x 2 (gemv)
#define KS_TOTAL 838784

// ---------------- helpers ----------------
__device__ __forceinline__ float tf32r(float x) {
    uint32_t r; asm("cvt.rna.tf32.f32 %0, %1;" : "=r"(r) : "f"(x));
    return __uint_as_float(r);
}

// ---------------- kernels ----------------

__global__ void k_prep(const float* __restrict__ p0, const float* __restrict__ v0,
                       const float* __restrict__ a, const float* __restrict__ other,
                       const float* __restrict__ v0enc)
{
    int i = blockIdx.x*blockDim.x + threadIdx.x;
    if (i >= BQ) return;
    float v0x = v0[i*2], v0y = v0[i*2+1];
    float v1x = v0x + 0.1f*a[i*2], v1y = v0y + 0.1f*a[i*2+1];
    g_p1[i*2]   = p0[i*2]   + 0.05f*(v0x+v1x);
    g_p1[i*2+1] = p0[i*2+1] + 0.05f*(v0y+v1y);
    float* f = g_feats + i*40;
    f[0]=v1x; f[1]=v1y;
    #pragma unroll
    for (int c=0;c<3;c++){ f[2+c*2]=other[(i*3+c)*2]; f[3+c*2]=other[(i*3+c)*2+1]; }
    #pragma unroll
    for (int c=0;c<16;c++){ f[8+c*2]=v0enc[(i*16+c)*2]; f[9+c*2]=v0enc[(i*16+c)*2+1]; }
}

__global__ void k_compact(const float* __restrict__ src, const float* __restrict__ qry,
                          const float* __restrict__ mask,
                          uint2* __restrict__ list, int* __restrict__ cnt)
{
    int warp = (blockIdx.x*blockDim.x + threadIdx.x) >> 5;
    int lane = threadIdx.x & 31;
    if (warp >= BQ) return;
    int b = warp >> 9, q = warp & 511;
    float qx = qry[(b*NN+q)*2], qy = qry[(b*NN+q)*2+1];
    const float* mrow = mask + (size_t)warp*NN;
    uint2* lrow = list + (size_t)warp*NN;
    int base = 0;
    for (int c = 0; c < NN; c += 32) {
        int s = c + lane;
        float rx = src[(b*NN+s)*2]   - qx;
        float ry = src[(b*NN+s)*2+1] - qy;
        float d2 = rx*rx + ry*ry;
        float m = mrow[s];
        float win = 1.0f - d2*(1.0f/1600.0f);
        bool on = (win > 0.f) && (m != 0.f);
        float wv = 0.f; int kidx = 0;
        if (on) {
            wv = win*win*win*m;
            float dist = sqrtf(d2 + 1e-9f);
            int rb = (int)(dist*(3.0f/40.0f)); if (rb > 2) rb = 2;
            int tb = ((int)floorf((atan2f(ry,rx) + PI_F)*(16.0f/(2.0f*PI_F)))) & 15;
            kidx = rb*16 + tb;
        }
        unsigned mk = __ballot_sync(0xffffffffu, on);
        if (on) {
            int pos = base + __popc(mk & ((1u<<lane)-1u));
            lrow[pos] = make_uint2(__float_as_uint(wv), (unsigned)((kidx<<16) | s));
        }
        base += __popc(mk);
    }
    if (lane == 0) cnt[warp] = base;
}

// ---- steered-kernel assembly: seg-constant divisions + smem trig table ----
struct SteerArgs { const float* Wc[6]; const float* Ad[6]; const float* Bd[6]; };

template<int O, int I, int COLS, int DOFF, int K, bool TC>
__device__ __forceinline__ float steer_val(int idx, const float* __restrict__ Wc,
                                           const float* __restrict__ Ad,
                                           const float* __restrict__ Bd,
                                           const float* tc, const float* ts)
{
    constexpr int IV = 2*I;
    int row, col;
    if (TC) { col = idx / K; row = idx - col*K; }
    else    { row = idx / COLS; col = idx - row*COLS; }
    float val = 0.f;
    if (row < KBINS*IV) {
        if (col < 2*O) {
            int k = row / IV, iv = row - k*IV, i = iv>>1, v = iv&1;
            int o = col>>1, u = col&1;
            int t = k & 15;
            float c = tc[t], s = ts[t];
            float R[2][2] = {{c,-s},{s,c}};
            const float* Wb = Wc + (((long long)k*O + o)*I + i)*4;
            val = R[u][0]*(Wb[0]*R[v][0] + Wb[1]*R[v][1])
                + R[u][1]*(Wb[2]*R[v][0] + Wb[3]*R[v][1]);
        }
    } else if (row < KBINS*IV + IV) {
        if (DOFF >= 0 && col >= DOFF && col < DOFF + 2*O) {
            int iv = row - KBINS*IV, i = iv>>1, v = iv&1;
            int oc = col - DOFF, o = oc>>1, u = oc&1;
            if (u == v) val = Ad[o*I+i];
            else        val = (u==0) ? -Bd[o*I+i] : Bd[o*I+i];
        }
    }
    return val;
}

__global__ void k_steer_all(SteerArgs args)
{
    __shared__ float tc[16], ts[16];
    if (threadIdx.x < 16) {
        float th = (threadIdx.x + 0.5f)*(2.0f*PI_F/16.0f) - PI_F;
        tc[threadIdx.x] = cosf(th);
        ts[threadIdx.x] = sinf(th);
    }
    __syncthreads();
    int gidx = blockIdx.x*blockDim.x + threadIdx.x;
    if (gidx >= KS_TOTAL) return;
    float val; bool rnd;
    if (gidx < OFF1B) {
        val = steer_val<16,20,64,32,1984,true>(gidx-OFF1A, args.Wc[0], args.Ad[0], args.Bd[0], tc, ts);
        rnd = true;
    } else if (gidx < OFFL1) {
        val = steer_val<16,1,32,-1,96,false>(gidx-OFF1B, args.Wc[1], 0, 0, tc, ts);
        rnd = false;
    } else if (gidx < OFFL2) {
        val = steer_val<32,48,64,0,4704,true>(gidx-OFFL1, args.Wc[2], args.Ad[2], args.Bd[2], tc, ts);
        rnd = true;
    } else if (gidx < OFFL3) {
        val = steer_val<32,32,64,0,3136,true>(gidx-OFFL2, args.Wc[3], args.Ad[3], args.Bd[3], tc, ts);
        rnd = true;
    } else if (gidx < OFFL4) {
        val = steer_val<32,32,64,0,3136,true>(gidx-OFFL3, args.Wc[4], args.Ad[4], args.Bd[4], tc, ts);
        rnd = true;
    } else {
        val = steer_val<1,32,2,0,3136,false>(gidx-OFFL4, args.Wc[5], args.Ad[5], args.Bd[5], tc, ts);
        rnd = false;
    }
    g_KS[gidx] = rnd ? tf32r(val) : val;
}

// ---- fluid binning: G=4 replicated accumulators, deterministic reduce ----
template<int IV, int LD, bool RND>
__global__ void k_bin(const float* __restrict__ feats)
{
    constexpr int HV = IV/2;
    constexpr int G = 4;
    extern __shared__ float smem_f[];
    float2* sM = (float2*)smem_f;                       // [G][KBINS*HV]
    uint2*  sl = (uint2*)(smem_f + G*KBINS*IV);         // [512]
    int bq = blockIdx.x, tid = threadIdx.x, b = bq >> 9;
    int T = blockDim.x;
    int cnt = g_cnt[bq];
    const uint2* lrow = g_list + (size_t)bq*NN;
    for (int i = tid; i < cnt; i += T) sl[i] = lrow[i];
    float2 z = make_float2(0.f, 0.f);
    for (int i = tid; i < G*KBINS*HV; i += T) sM[i] = z;
    __syncthreads();
    int lane = tid % HV, grp = tid / HV;
    if (grp < G) {
        const float2* fb = (const float2*)feats + (size_t)(b*NN)*HV + lane;
        float2* m = sM + grp*KBINS*HV + lane;
        for (int e = grp; e < cnt; e += G) {
            uint2 pk = sl[e];
            float ws = __uint_as_float(pk.x);
            int s = pk.y & 0xffff, k = pk.y >> 16;
            float2 f = fb[(size_t)s*HV];
            float2 acc = m[k*HV];
            acc.x += ws*f.x; acc.y += ws*f.y;
            m[k*HV] = acc;
        }
    }
    __syncthreads();
    float* xr = g_X + (size_t)bq*LD;
    const float* s0 = smem_f;
    for (int i = tid; i < KBINS*IV; i += T) {
        float v = ((s0[i] + s0[KBINS*IV + i]) + s0[2*KBINS*IV + i]) + s0[3*KBINS*IV + i];
        xr[i] = RND ? tf32r(v) : v;
    }
    for (int i = tid; i < IV; i += T) {
        float v = feats[(size_t)bq*IV + i];
        xr[KBINS*IV + i] = RND ? tf32r(v) : v;
    }
    for (int i = 49*IV + tid; i < LD; i += T) xr[i] = 0.f;
}

__global__ void k_bino(const float* __restrict__ box_feats)
{
    __shared__ uint2 sl[NN];
    __shared__ float sbf[NN*2];
    int bq = blockIdx.x, tid = threadIdx.x, b = bq >> 9;
    int cnt = g_cnto[bq];
    const uint2* lrow = g_listo + (size_t)bq*NN;
    for (int i = tid; i < cnt; i += blockDim.x) sl[i] = lrow[i];
    for (int i = tid; i < NN*2; i += blockDim.x) sbf[i] = box_feats[b*NN*2 + i];
    __syncthreads();
    if (tid < 96) {
        int k = tid >> 1, v = tid & 1;
        float acc = 0.f;
        for (int e = 0; e < cnt; ++e) {
            uint2 pk = sl[e];
            if ((int)(pk.y >> 16) == k)
                acc += __uint_as_float(pk.x) * sbf[(pk.y & 0xffff)*2 + v];
        }
        g_Xo[bq*96 + tid] = acc;
    }
}

// ---- tensor-core GEMM via mma.sync tf32 (see R5 notes) ----
__global__ void k_gemm_mma(const float* __restrict__ X, const float* __restrict__ Wt, int inner)
{
    __shared__ float As[128][36];
    __shared__ float Bs[64][36];
    int tid = threadIdx.x, lane = tid & 31, warp = tid >> 5;
    int row0 = blockIdx.x * 128;
    int ntiles = inner / 32;
    int per = (ntiles + NSPLIT - 1) / NSPLIT;
    int t0 = blockIdx.y * per;
    int t1 = min(ntiles, t0 + per);
    int g = lane >> 2, q = lane & 3;

    float acc[2][8][4];
    #pragma unroll
    for (int a = 0; a < 2; ++a)
        #pragma unroll
        for (int b = 0; b < 8; ++b)
            #pragma unroll
            for (int c = 0; c < 4; ++c) acc[a][b][c] = 0.f;

    for (int t = t0; t < t1; ++t) {
        int kk = t*32;
        #pragma unroll
        for (int r = 0; r < 8; ++r) {
            int idx = tid + r*128;
            int m = idx >> 3, c4 = (idx & 7)*4;
            float4 v = *(const float4*)&X[(size_t)(row0+m)*inner + kk + c4];
            *(float4*)&As[m][c4] = v;
        }
        #pragma unroll
        for (int r = 0; r < 4; ++r) {
            int idx = tid + r*128;
            int n = idx >> 3, c4 = (idx & 7)*4;
            float4 v = *(const float4*)&Wt[(size_t)n*inner + kk + c4];
            *(float4*)&Bs[n][c4] = v;
        }
        __syncthreads();
        #pragma unroll
        for (int k8 = 0; k8 < 4; ++k8) {
            int kb = k8*8;
            uint32_t bf0[8], bf1[8];
            #pragma unroll
            for (int nt = 0; nt < 8; ++nt) {
                bf0[nt] = __float_as_uint(Bs[nt*8 + g][kb + q]);
                bf1[nt] = __float_as_uint(Bs[nt*8 + g][kb + q + 4]);
            }
            #pragma unroll
            for (int mt = 0; mt < 2; ++mt) {
                int mr = warp*32 + mt*16 + g;
                uint32_t a0 = __float_as_uint(As[mr][kb+q]);
                uint32_t a1 = __float_as_uint(As[mr+8][kb+q]);
                uint32_t a2 = __float_as_uint(As[mr][kb+q+4]);
                uint32_t a3 = __float_as_uint(As[mr+8][kb+q+4]);
                #pragma unroll
                for (int nt = 0; nt < 8; ++nt) {
                    asm volatile(
                        "mma.sync.aligned.m16n8k8.row.col.f32.tf32.tf32.f32 "
                        "{%0,%1,%2,%3}, {%4,%5,%6,%7}, {%8,%9}, {%0,%1,%2,%3};"
                        : "+f"(acc[mt][nt][0]), "+f"(acc[mt][nt][1]),
                          "+f"(acc[mt][nt][2]), "+f"(acc[mt][nt][3])
                        : "r"(a0), "r"(a1), "r"(a2), "r"(a3),
                          "r"(bf0[nt]), "r"(bf1[nt]));
                }
            }
        }
        __syncthreads();
    }
    float* pb = g_part + ((size_t)blockIdx.y*BQ + row0)*64;
    #pragma unroll
    for (int mt = 0; mt < 2; ++mt) {
        int r0 = warp*32 + mt*16 + g;
        #pragma unroll
        for (int nt = 0; nt < 8; ++nt) {
            int c = nt*8 + q*2;
            *(float2*)&pb[(size_t)r0*64 + c]     = make_float2(acc[mt][nt][0], acc[mt][nt][1]);
            *(float2*)&pb[(size_t)(r0+8)*64 + c] = make_float2(acc[mt][nt][2], acc[mt][nt][3]);
        }
    }
}

// ---- fused stage-1 finish: obstacle GEMM + fluid partial reduce + nonlin -> g_feats ----
__global__ void k_fin1(const float* __restrict__ KSo)
{
    int idx = blockIdx.x*blockDim.x + threadIdx.x;
    if (idx >= BQ*48) return;
    int row = idx / 48, ch = idx - row*48;
    float x = 0.f, y = 0.f;
    if (ch < 16) {
        const float* xr = g_Xo + row*96;
        #pragma unroll 8
        for (int k = 0; k < 96; ++k) {
            float xv = xr[k];
            x += xv * KSo[k*32 + 2*ch];
            y += xv * KSo[k*32 + 2*ch + 1];
        }
    } else {
        int c = ch - 16;
        #pragma unroll
        for (int s = 0; s < NSPLIT; ++s) {
            const float* p = g_part + ((size_t)s*BQ + row)*64 + 2*c;
            x += p[0]; y += p[1];
        }
    }
    float mag = x*x + y*y + 1e-6f;
    float sc = fmaxf(mag - 0.2f, 0.f) / mag;
    g_feats[row*96 + 2*ch]   = x*sc;
    g_feats[row*96 + 2*ch+1] = y*sc;
}

// fused: sum partials + residual + nonlinearity (64-col layers)
__global__ void k_finnl(float* __restrict__ out, const float* __restrict__ res)
{
    int idx = blockIdx.x*blockDim.x + threadIdx.x;
    if (idx >= BQ*32) return;
    int row = idx >> 5, c = idx & 31;
    float x = 0.f, y = 0.f;
    #pragma unroll
    for (int s = 0; s < NSPLIT; ++s) {
        const float* p = g_part + ((size_t)s*BQ + row)*64 + c*2;
        x += p[0]; y += p[1];
    }
    if (res) { x += res[row*64 + c*2]; y += res[row*64 + c*2+1]; }
    out[row*64 + c*2] = x; out[row*64 + c*2+1] = y;
    float mag = x*x + y*y + 1e-6f;
    float sc = fmaxf(mag - 0.2f, 0.f) / mag;
    g_feats[row*64 + c*2]   = x*sc;
    g_feats[row*64 + c*2+1] = y*sc;
}

// layer 4 GEMV fused with final correction
__global__ void k_gemv_final(const float* __restrict__ X, const float* __restrict__ Wm,
                             int inner, const float* __restrict__ p0,
                             float* __restrict__ dout, int half)
{
    __shared__ float Wsh[3136*2];
    int tid = threadIdx.x;
    for (int i = tid; i < inner*2; i += blockDim.x) Wsh[i] = Wm[i];
    __syncthreads();
    int warp = tid >> 5, lane = tid & 31;
    int row = blockIdx.x*8 + warp;
    const float* xr = X + (size_t)row*inner;
    float a0 = 0.f, a1 = 0.f;
    for (int k = lane; k < inner; k += 32) {
        float x = xr[k];
        a0 += x*Wsh[k*2];
        a1 += x*Wsh[k*2+1];
    }
    #pragma unroll
    for (int o = 16; o; o >>= 1) {
        a0 += __shfl_down_sync(0xffffffffu, a0, o);
        a1 += __shfl_down_sync(0xffffffffu, a1, o);
    }
    if (lane == 0) {
        float px = g_p1[row*2]   + a0*(1.0f/128.0f);
        float py = g_p1[row*2+1] + a1*(1.0f/128.0f);
        dout[row*2]   = px;
        dout[row*2+1] = py;
        dout[half + row*2]   = (px - p0[row*2])  *10.0f;
        dout[half + row*2+1] = (py - p0[row*2+1])*10.0f;
    }
}

// ---------------- host driver ----------------
extern "C" void kernel_launch(void* const* d_in, const int* in_sizes, int n_in,
                              void* d_out, int out_size)
{
    const float* v0_enc = (const float*)d_in[1];
    const float* p0     = (const float*)d_in[2];
    const float* v0     = (const float*)d_in[3];
    const float* a      = (const float*)d_in[4];
    const float* other  = (const float*)d_in[5];
    const float* box    = (const float*)d_in[6];
    const float* boxf   = (const float*)d_in[7];
    const float* fmask  = (const float*)d_in[8];
    const float* bmask  = (const float*)d_in[9];
    float* dout = (float*)d_out;
    int half = out_size / 2;

    float *X, *KS, *outA, *outB, *feats, *p1;
    uint2 *list, *listo; int *cnt, *cnto;
    cudaGetSymbolAddress((void**)&X,     g_X);
    cudaGetSymbolAddress((void**)&KS,    g_KS);
    cudaGetSymbolAddress((void**)&outA,  g_outA);
    cudaGetSymbolAddress((void**)&outB,  g_outB);
    cudaGetSymbolAddress((void**)&feats, g_feats);
    cudaGetSymbolAddress((void**)&p1,    g_p1);
    cudaGetSymbolAddress((void**)&list,  g_list);
    cudaGetSymbolAddress((void**)&listo, g_listo);
    cudaGetSymbolAddress((void**)&cnt,   g_cnt);
    cudaGetSymbolAddress((void**)&cnto,  g_cnto);

    // dynamic-smem opt-in for the grouped bin kernels
    const int sb40 = 4*KBINS*40*4 + NN*8;    // 34816
    const int sb64 = 4*KBINS*64*4 + NN*8;    // 53248
    const int sb96 = 4*KBINS*96*4 + NN*8;    // 77824
    cudaFuncSetAttribute((const void*)k_bin<40,1984,true>,  cudaFuncAttributeMaxDynamicSharedMemorySize, sb40);
    cudaFuncSetAttribute((const void*)k_bin<96,4704,true>,  cudaFuncAttributeMaxDynamicSharedMemorySize, sb96);
    cudaFuncSetAttribute((const void*)k_bin<64,3136,true>,  cudaFuncAttributeMaxDynamicSharedMemorySize, sb64);
    cudaFuncSetAttribute((const void*)k_bin<64,3136,false>, cudaFuncAttributeMaxDynamicSharedMemorySize, sb64);

    SteerArgs sa;
    sa.Wc[0] = (const float*)d_in[10]; sa.Ad[0] = (const float*)d_in[12]; sa.Bd[0] = (const float*)d_in[13];
    sa.Wc[1] = (const float*)d_in[11]; sa.Ad[1] = nullptr;                sa.Bd[1] = nullptr;
    sa.Wc[2] = (const float*)d_in[14]; sa.Ad[2] = (const float*)d_in[15]; sa.Bd[2] = (const float*)d_in[16];
    sa.Wc[3] = (const float*)d_in[17]; sa.Ad[3] = (const float*)d_in[18]; sa.Bd[3] = (const float*)d_in[19];
    sa.Wc[4] = (const float*)d_in[20]; sa.Ad[4] = (const float*)d_in[21]; sa.Bd[4] = (const float*)d_in[22];
    sa.Wc[5] = (const float*)d_in[23]; sa.Ad[5] = (const float*)d_in[24]; sa.Bd[5] = (const float*)d_in[25];

    dim3 gg(BQ/128, NSPLIT);   // 16 x 8 = 128 CTAs

    // 1. integrate + 20-ch fluid feats
    k_prep<<<(BQ+127)/128, 128>>>(p0, v0, a, other, v0_enc);
    // 2. fused geometry + compaction
    k_compact<<<BQ/8, 256>>>(p1, p1, fmask, list, cnt);
    k_compact<<<BQ/8, 256>>>(box, p1, bmask, listo, cnto);
    // 3. stage-1 fluid binning (4th launch -> profiled)
    k_bin<40,1984,true><<<BQ, 96, sb40>>>(feats);
    // 4. obstacle binning + steered matrices
    k_bino<<<BQ, 128>>>(boxf);
    k_steer_all<<<(KS_TOTAL+255)/256, 256>>>(sa);
    // 5. stage 1 GEMM + fused finish (obstacle GEMM + partial reduce + nonlin)
    k_gemm_mma<<<gg, 128>>>(X, KS+OFF1A, 1984);
    k_fin1<<<(BQ*48+255)/256, 256>>>(KS+OFF1B);
    // 6. layer 1: 48 -> 32
    k_bin<96,4704,true><<<BQ, 192, sb96>>>(feats);
    k_gemm_mma<<<gg, 128>>>(X, KS+OFFL1, 4704);
    k_finnl<<<(BQ*32+255)/256, 256>>>(outB, nullptr);
    // 7. layer 2: 32 -> 32, residual
    k_bin<64,3136,true><<<BQ, 128, sb64>>>(feats);
    k_gemm_mma<<<gg, 128>>>(X, KS+OFFL2, 3136);
    k_finnl<<<(BQ*32+255)/256, 256>>>(outA, outB);
    // 8. layer 3: 32 -> 32, residual
    k_bin<64,3136,true><<<BQ, 128, sb64>>>(feats);
    k_gemm_mma<<<gg, 128>>>(X, KS+OFFL3, 3136);
    k_finnl<<<(BQ*32+255)/256, 256>>>(outB, outA);
    // 9. layer 4: 32 -> 1 (GEMV fused with final correction)
    k_bin<64,3136,false><<<BQ, 128, sb64>>>(feats);
    k_gemv_final<<<BQ/8, 256>>>(X, KS+OFFL4, 3136, p0, dout, half);
}

// round 7
// speedup vs baseline: 3.0742x; 1.4485x over previous
#include <cuda_runtime.h>
#include <math.h>
#include <stdint.h>

#define BB 4
#define NN 512
#define BQ 2048
#define KBINS 48
#define PI_F 3.14159265358979f
#define NSPLIT 8

typedef unsigned long long ull;

// ---------------- device scratch ----------------
__device__ __align__(16) float g_X[BQ * 4704];
__device__ __align__(16) float g_Xo[BQ * 96];
__device__ __align__(16) uint2 g_list [BQ * NN];
__device__ int   g_cnt [BQ];
__device__ int   g_boff[BQ * 49];
__device__ __align__(16) uint2 g_listo[BQ * NN];
__device__ int   g_cnto[BQ];
__device__ int   g_boffo[BQ * 49];
__device__ __align__(16) float g_KS[838784];
__device__ __align__(16) float g_part[NSPLIT * BQ * 64];
__device__ __align__(16) float g_outA[BQ * 96];
__device__ __align__(16) float g_outB[BQ * 96];
__device__ __align__(16) float g_feats[BQ * 96];
__device__ float g_p1[BQ * 2];

// KS segment offsets (floats) — contiguous prefix sums
#define OFF1A 0        // TC: 64 x 1984 (transposed, ld=1984)
#define OFF1B 126976   // row-major 96 x 32 (obstacle)
#define OFFL1 130048   // TC: 64 x 4704
#define OFFL2 431104   // TC: 64 x 3136
#define OFFL3 631808   // TC: 64 x 3136
#define OFFL4 832512   // row-major 3136 x 2 (gemv)
#define KS_TOTAL 838784

// ---------------- helpers ----------------
__device__ __forceinline__ float tf32r(float x) {
    uint32_t r; asm("cvt.rna.tf32.f32 %0, %1;" : "=r"(r) : "f"(x));
    return __uint_as_float(r);
}

// ---------------- kernels ----------------

__global__ void k_prep(const float* __restrict__ p0, const float* __restrict__ v0,
                       const float* __restrict__ a, const float* __restrict__ other,
                       const float* __restrict__ v0enc)
{
    int i = blockIdx.x*blockDim.x + threadIdx.x;
    if (i >= BQ) return;
    float v0x = v0[i*2], v0y = v0[i*2+1];
    float v1x = v0x + 0.1f*a[i*2], v1y = v0y + 0.1f*a[i*2+1];
    g_p1[i*2]   = p0[i*2]   + 0.05f*(v0x+v1x);
    g_p1[i*2+1] = p0[i*2+1] + 0.05f*(v0y+v1y);
    float* f = g_feats + i*40;
    f[0]=v1x; f[1]=v1y;
    #pragma unroll
    for (int c=0;c<3;c++){ f[2+c*2]=other[(i*3+c)*2]; f[3+c*2]=other[(i*3+c)*2+1]; }
    #pragma unroll
    for (int c=0;c<16;c++){ f[8+c*2]=v0enc[(i*16+c)*2]; f[9+c*2]=v0enc[(i*16+c)*2+1]; }
}

// geometry + compaction + stable counting sort by bin. One warp per query.
__global__ void k_compact(const float* __restrict__ src, const float* __restrict__ qry,
                          const float* __restrict__ mask,
                          uint2* __restrict__ list, int* __restrict__ cnt,
                          int* __restrict__ boff)
{
    __shared__ uint2 s_tmp[8][NN];
    __shared__ int s_cnt[8][KBINS];
    __shared__ int s_off[8][KBINS+1];
    __shared__ int s_run[8][KBINS];
    int wIn = threadIdx.x >> 5;
    int lane = threadIdx.x & 31;
    int warp = blockIdx.x*8 + wIn;
    int b = warp >> 9, q = warp & 511;
    float qx = qry[(b*NN+q)*2], qy = qry[(b*NN+q)*2+1];
    const float* mrow = mask + (size_t)warp*NN;
    for (int i = lane; i < KBINS; i += 32) { s_cnt[wIn][i] = 0; s_run[wIn][i] = 0; }
    __syncwarp();
    int base = 0;
    for (int c = 0; c < NN; c += 32) {
        int s = c + lane;
        float rx = src[(b*NN+s)*2]   - qx;
        float ry = src[(b*NN+s)*2+1] - qy;
        float d2 = rx*rx + ry*ry;
        float m = mrow[s];
        float win = 1.0f - d2*(1.0f/1600.0f);
        bool on = (win > 0.f) && (m != 0.f);
        float wv = 0.f; int kidx = 0;
        if (on) {
            wv = win*win*win*m;
            float dist = sqrtf(d2 + 1e-9f);
            int rb = (int)(dist*(3.0f/40.0f)); if (rb > 2) rb = 2;
            int tb = ((int)floorf((atan2f(ry,rx) + PI_F)*(16.0f/(2.0f*PI_F)))) & 15;
            kidx = rb*16 + tb;
        }
        unsigned mk = __ballot_sync(0xffffffffu, on);
        if (on) {
            int pos = base + __popc(mk & ((1u<<lane)-1u));
            s_tmp[wIn][pos] = make_uint2(__float_as_uint(wv), (unsigned)((kidx<<16) | s));
        }
        base += __popc(mk);
    }
    __syncwarp();
    // histogram (counts order-independent -> deterministic)
    for (int e = lane; e < base; e += 32)
        atomicAdd(&s_cnt[wIn][s_tmp[wIn][e].y >> 16], 1);
    __syncwarp();
    if (lane == 0) {
        int acc = 0;
        #pragma unroll
        for (int k = 0; k < KBINS; ++k) { s_off[wIn][k] = acc; acc += s_cnt[wIn][k]; }
        s_off[wIn][KBINS] = acc;
    }
    __syncwarp();
    // stable scatter (preserves s-order within bin)
    uint2* lrow = list + (size_t)warp*NN;
    for (int c = 0; c < base; c += 32) {
        int e = c + lane;
        bool valid = e < base;
        unsigned msk = __ballot_sync(0xffffffffu, valid);
        int bin = 0, rank = 0, gcnt = 0; bool lead = false; uint2 pk;
        if (valid) {
            pk = s_tmp[wIn][e];
            bin = pk.y >> 16;
            unsigned grp = __match_any_sync(msk, bin);
            rank = __popc(grp & ((1u<<lane)-1u));
            lead = ((__ffs(grp)-1) == lane);
            gcnt = __popc(grp);
        }
        int runv = valid ? s_run[wIn][bin] : 0;
        __syncwarp();
        if (valid) {
            lrow[s_off[wIn][bin] + runv + rank] = pk;
            if (lead) s_run[wIn][bin] = runv + gcnt;
        }
        __syncwarp();
    }
    for (int k = lane; k < KBINS+1; k += 32) boff[warp*49 + k] = s_off[wIn][k];
    if (lane == 0) cnt[warp] = base;
}

// ---- steered-kernel assembly: seg-constant divisions + smem trig table ----
struct SteerArgs { const float* Wc[6]; const float* Ad[6]; const float* Bd[6]; };

template<int O, int I, int COLS, int DOFF, int K, bool TC>
__device__ __forceinline__ float steer_val(int idx, const float* __restrict__ Wc,
                                           const float* __restrict__ Ad,
                                           const float* __restrict__ Bd,
                                           const float* tc, const float* ts)
{
    constexpr int IV = 2*I;
    int row, col;
    if (TC) { col = idx / K; row = idx - col*K; }
    else    { row = idx / COLS; col = idx - row*COLS; }
    float val = 0.f;
    if (row < KBINS*IV) {
        if (col < 2*O) {
            int k = row / IV, iv = row - k*IV, i = iv>>1, v = iv&1;
            int o = col>>1, u = col&1;
            int t = k & 15;
            float c = tc[t], s = ts[t];
            float R[2][2] = {{c,-s},{s,c}};
            const float* Wb = Wc + (((long long)k*O + o)*I + i)*4;
            val = R[u][0]*(Wb[0]*R[v][0] + Wb[1]*R[v][1])
                + R[u][1]*(Wb[2]*R[v][0] + Wb[3]*R[v][1]);
        }
    } else if (row < KBINS*IV + IV) {
        if (DOFF >= 0 && col >= DOFF && col < DOFF + 2*O) {
            int iv = row - KBINS*IV, i = iv>>1, v = iv&1;
            int oc = col - DOFF, o = oc>>1, u = oc&1;
            if (u == v) val = Ad[o*I+i];
            else        val = (u==0) ? -Bd[o*I+i] : Bd[o*I+i];
        }
    }
    return val;
}

__global__ void k_steer_all(SteerArgs args)
{
    __shared__ float tc[16], ts[16];
    if (threadIdx.x < 16) {
        float th = (threadIdx.x + 0.5f)*(2.0f*PI_F/16.0f) - PI_F;
        tc[threadIdx.x] = cosf(th);
        ts[threadIdx.x] = sinf(th);
    }
    __syncthreads();
    int gidx = blockIdx.x*blockDim.x + threadIdx.x;
    if (gidx >= KS_TOTAL) return;
    float val; bool rnd;
    if (gidx < OFF1B) {
        val = steer_val<16,20,64,32,1984,true>(gidx-OFF1A, args.Wc[0], args.Ad[0], args.Bd[0], tc, ts);
        rnd = true;
    } else if (gidx < OFFL1) {
        val = steer_val<16,1,32,-1,96,false>(gidx-OFF1B, args.Wc[1], 0, 0, tc, ts);
        rnd = false;
    } else if (gidx < OFFL2) {
        val = steer_val<32,48,64,0,4704,true>(gidx-OFFL1, args.Wc[2], args.Ad[2], args.Bd[2], tc, ts);
        rnd = true;
    } else if (gidx < OFFL3) {
        val = steer_val<32,32,64,0,3136,true>(gidx-OFFL2, args.Wc[3], args.Ad[3], args.Bd[3], tc, ts);
        rnd = true;
    } else if (gidx < OFFL4) {
        val = steer_val<32,32,64,0,3136,true>(gidx-OFFL3, args.Wc[4], args.Ad[4], args.Bd[4], tc, ts);
        rnd = true;
    } else {
        val = steer_val<1,32,2,0,3136,false>(gidx-OFFL4, args.Wc[5], args.Ad[5], args.Bd[5], tc, ts);
        rnd = false;
    }
    g_KS[gidx] = rnd ? tf32r(val) : val;
}

// ---- fluid binning: sorted segments, register accumulation, direct gmem write ----
template<int IV, int LD, bool RND>
__global__ void k_bin(const float* __restrict__ feats)
{
    constexpr int HV = IV/2;
    constexpr int NG = (IV==40) ? 12 : ((IV==64) ? 8 : 5);
    constexpr int T  = HV*NG;          // 240 / 256 / 240
    __shared__ uint2 sl[NN];
    __shared__ int sb[KBINS+1];
    int bq = blockIdx.x, tid = threadIdx.x, b = bq >> 9;
    int cnt = g_cnt[bq];
    const uint2* lrow = g_list + (size_t)bq*NN;
    for (int i = tid; i < cnt; i += T) sl[i] = lrow[i];
    for (int i = tid; i < KBINS+1; i += T) sb[i] = g_boff[bq*49 + i];
    __syncthreads();
    int col = tid % HV, grp = tid / HV;
    const float2* fb = (const float2*)feats + (size_t)(b*NN)*HV + col;
    float* xr = g_X + (size_t)bq*LD;
    for (int k = grp; k < KBINS; k += NG) {
        float2 acc = make_float2(0.f, 0.f);
        int e1 = sb[k+1];
        for (int e = sb[k]; e < e1; ++e) {
            uint2 pk = sl[e];
            float ws = __uint_as_float(pk.x);
            int s = pk.y & 0xffff;
            float2 f = fb[(size_t)s*HV];
            acc.x += ws*f.x; acc.y += ws*f.y;
        }
        if (RND) { acc.x = tf32r(acc.x); acc.y = tf32r(acc.y); }
        *(float2*)&xr[k*IV + 2*col] = acc;
    }
    for (int i = tid; i < IV; i += T) {
        float v = feats[(size_t)bq*IV + i];
        xr[KBINS*IV + i] = RND ? tf32r(v) : v;
    }
    for (int i = 49*IV + tid; i < LD; i += T) xr[i] = 0.f;
}

// obstacle binning over sorted segments
__global__ void k_bino(const float* __restrict__ box_feats)
{
    __shared__ uint2 sl[NN];
    __shared__ float sbf[NN*2];
    __shared__ int sb[KBINS+1];
    int bq = blockIdx.x, tid = threadIdx.x, b = bq >> 9;
    int cnt = g_cnto[bq];
    const uint2* lrow = g_listo + (size_t)bq*NN;
    for (int i = tid; i < cnt; i += blockDim.x) sl[i] = lrow[i];
    for (int i = tid; i < KBINS+1; i += blockDim.x) sb[i] = g_boffo[bq*49 + i];
    for (int i = tid; i < NN*2; i += blockDim.x) sbf[i] = box_feats[b*NN*2 + i];
    __syncthreads();
    if (tid < 96) {
        int k = tid >> 1, v = tid & 1;
        float acc = 0.f;
        int e1 = sb[k+1];
        for (int e = sb[k]; e < e1; ++e) {
            uint2 pk = sl[e];
            acc += __uint_as_float(pk.x) * sbf[(pk.y & 0xffff)*2 + v];
        }
        g_Xo[bq*96 + tid] = acc;
    }
}

// ---- tensor-core GEMM via mma.sync tf32 ----
__global__ void k_gemm_mma(const float* __restrict__ X, const float* __restrict__ Wt, int inner)
{
    __shared__ float As[128][36];
    __shared__ float Bs[64][36];
    int tid = threadIdx.x, lane = tid & 31, warp = tid >> 5;
    int row0 = blockIdx.x * 128;
    int ntiles = inner / 32;
    int per = (ntiles + NSPLIT - 1) / NSPLIT;
    int t0 = blockIdx.y * per;
    int t1 = min(ntiles, t0 + per);
    int g = lane >> 2, q = lane & 3;

    float acc[2][8][4];
    #pragma unroll
    for (int a = 0; a < 2; ++a)
        #pragma unroll
        for (int b = 0; b < 8; ++b)
            #pragma unroll
            for (int c = 0; c < 4; ++c) acc[a][b][c] = 0.f;

    for (int t = t0; t < t1; ++t) {
        int kk = t*32;
        #pragma unroll
        for (int r = 0; r < 8; ++r) {
            int idx = tid + r*128;
            int m = idx >> 3, c4 = (idx & 7)*4;
            float4 v = *(const float4*)&X[(size_t)(row0+m)*inner + kk + c4];
            *(float4*)&As[m][c4] = v;
        }
        #pragma unroll
        for (int r = 0; r < 4; ++r) {
            int idx = tid + r*128;
            int n = idx >> 3, c4 = (idx & 7)*4;
            float4 v = *(const float4*)&Wt[(size_t)n*inner + kk + c4];
            *(float4*)&Bs[n][c4] = v;
        }
        __syncthreads();
        #pragma unroll
        for (int k8 = 0; k8 < 4; ++k8) {
            int kb = k8*8;
            uint32_t bf0[8], bf1[8];
            #pragma unroll
            for (int nt = 0; nt < 8; ++nt) {
                bf0[nt] = __float_as_uint(Bs[nt*8 + g][kb + q]);
                bf1[nt] = __float_as_uint(Bs[nt*8 + g][kb + q + 4]);
            }
            #pragma unroll
            for (int mt = 0; mt < 2; ++mt) {
                int mr = warp*32 + mt*16 + g;
                uint32_t a0 = __float_as_uint(As[mr][kb+q]);
                uint32_t a1 = __float_as_uint(As[mr+8][kb+q]);
                uint32_t a2 = __float_as_uint(As[mr][kb+q+4]);
                uint32_t a3 = __float_as_uint(As[mr+8][kb+q+4]);
                #pragma unroll
                for (int nt = 0; nt < 8; ++nt) {
                    asm volatile(
                        "mma.sync.aligned.m16n8k8.row.col.f32.tf32.tf32.f32 "
                        "{%0,%1,%2,%3}, {%4,%5,%6,%7}, {%8,%9}, {%0,%1,%2,%3};"
                        : "+f"(acc[mt][nt][0]), "+f"(acc[mt][nt][1]),
                          "+f"(acc[mt][nt][2]), "+f"(acc[mt][nt][3])
                        : "r"(a0), "r"(a1), "r"(a2), "r"(a3),
                          "r"(bf0[nt]), "r"(bf1[nt]));
                }
            }
        }
        __syncthreads();
    }
    float* pb = g_part + ((size_t)blockIdx.y*BQ + row0)*64;
    #pragma unroll
    for (int mt = 0; mt < 2; ++mt) {
        int r0 = warp*32 + mt*16 + g;
        #pragma unroll
        for (int nt = 0; nt < 8; ++nt) {
            int c = nt*8 + q*2;
            *(float2*)&pb[(size_t)r0*64 + c]     = make_float2(acc[mt][nt][0], acc[mt][nt][1]);
            *(float2*)&pb[(size_t)(r0+8)*64 + c] = make_float2(acc[mt][nt][2], acc[mt][nt][3]);
        }
    }
}

// ---- fused stage-1 finish: obstacle GEMM + fluid partial reduce + nonlin -> g_feats ----
__global__ void k_fin1(const float* __restrict__ KSo)
{
    int idx = blockIdx.x*blockDim.x + threadIdx.x;
    if (idx >= BQ*48) return;
    int row = idx / 48, ch = idx - row*48;
    float x = 0.f, y = 0.f;
    if (ch < 16) {
        const float* xr = g_Xo + row*96;
        #pragma unroll 8
        for (int k = 0; k < 96; ++k) {
            float xv = xr[k];
            x += xv * KSo[k*32 + 2*ch];
            y += xv * KSo[k*32 + 2*ch + 1];
        }
    } else {
        int c = ch - 16;
        #pragma unroll
        for (int s = 0; s < NSPLIT; ++s) {
            const float* p = g_part + ((size_t)s*BQ + row)*64 + 2*c;
            x += p[0]; y += p[1];
        }
    }
    float mag = x*x + y*y + 1e-6f;
    float sc = fmaxf(mag - 0.2f, 0.f) / mag;
    g_feats[row*96 + 2*ch]   = x*sc;
    g_feats[row*96 + 2*ch+1] = y*sc;
}

// fused: sum partials + residual + nonlinearity (64-col layers)
__global__ void k_finnl(float* __restrict__ out, const float* __restrict__ res)
{
    int idx = blockIdx.x*blockDim.x + threadIdx.x;
    if (idx >= BQ*32) return;
    int row = idx >> 5, c = idx & 31;
    float x = 0.f, y = 0.f;
    #pragma unroll
    for (int s = 0; s < NSPLIT; ++s) {
        const float* p = g_part + ((size_t)s*BQ + row)*64 + c*2;
        x += p[0]; y += p[1];
    }
    if (res) { x += res[row*64 + c*2]; y += res[row*64 + c*2+1]; }
    out[row*64 + c*2] = x; out[row*64 + c*2+1] = y;
    float mag = x*x + y*y + 1e-6f;
    float sc = fmaxf(mag - 0.2f, 0.f) / mag;
    g_feats[row*64 + c*2]   = x*sc;
    g_feats[row*64 + c*2+1] = y*sc;
}

// layer 4 GEMV fused with final correction
__global__ void k_gemv_final(const float* __restrict__ X, const float* __restrict__ Wm,
                             int inner, const float* __restrict__ p0,
                             float* __restrict__ dout, int half)
{
    __shared__ float Wsh[3136*2];
    int tid = threadIdx.x;
    for (int i = tid; i < inner*2; i += blockDim.x) Wsh[i] = Wm[i];
    __syncthreads();
    int warp = tid >> 5, lane = tid & 31;
    int row = blockIdx.x*8 + warp;
    const float* xr = X + (size_t)row*inner;
    float a0 = 0.f, a1 = 0.f;
    for (int k = lane; k < inner; k += 32) {
        float x = xr[k];
        a0 += x*Wsh[k*2];
        a1 += x*Wsh[k*2+1];
    }
    #pragma unroll
    for (int o = 16; o; o >>= 1) {
        a0 += __shfl_down_sync(0xffffffffu, a0, o);
        a1 += __shfl_down_sync(0xffffffffu, a1, o);
    }
    if (lane == 0) {
        float px = g_p1[row*2]   + a0*(1.0f/128.0f);
        float py = g_p1[row*2+1] + a1*(1.0f/128.0f);
        dout[row*2]   = px;
        dout[row*2+1] = py;
        dout[half + row*2]   = (px - p0[row*2])  *10.0f;
        dout[half + row*2+1] = (py - p0[row*2+1])*10.0f;
    }
}

// ---------------- host driver ----------------
extern "C" void kernel_launch(void* const* d_in, const int* in_sizes, int n_in,
                              void* d_out, int out_size)
{
    const float* v0_enc = (const float*)d_in[1];
    const float* p0     = (const float*)d_in[2];
    const float* v0     = (const float*)d_in[3];
    const float* a      = (const float*)d_in[4];
    const float* other  = (const float*)d_in[5];
    const float* box    = (const float*)d_in[6];
    const float* boxf   = (const float*)d_in[7];
    const float* fmask  = (const float*)d_in[8];
    const float* bmask  = (const float*)d_in[9];
    float* dout = (float*)d_out;
    int half = out_size / 2;

    float *X, *KS, *outA, *outB, *feats, *p1;
    uint2 *list, *listo; int *cnt, *cnto, *boff, *boffo;
    cudaGetSymbolAddress((void**)&X,     g_X);
    cudaGetSymbolAddress((void**)&KS,    g_KS);
    cudaGetSymbolAddress((void**)&outA,  g_outA);
    cudaGetSymbolAddress((void**)&outB,  g_outB);
    cudaGetSymbolAddress((void**)&feats, g_feats);
    cudaGetSymbolAddress((void**)&p1,    g_p1);
    cudaGetSymbolAddress((void**)&list,  g_list);
    cudaGetSymbolAddress((void**)&listo, g_listo);
    cudaGetSymbolAddress((void**)&cnt,   g_cnt);
    cudaGetSymbolAddress((void**)&cnto,  g_cnto);
    cudaGetSymbolAddress((void**)&boff,  g_boff);
    cudaGetSymbolAddress((void**)&boffo, g_boffo);

    SteerArgs sa;
    sa.Wc[0] = (const float*)d_in[10]; sa.Ad[0] = (const float*)d_in[12]; sa.Bd[0] = (const float*)d_in[13];
    sa.Wc[1] = (const float*)d_in[11]; sa.Ad[1] = nullptr;                sa.Bd[1] = nullptr;
    sa.Wc[2] = (const float*)d_in[14]; sa.Ad[2] = (const float*)d_in[15]; sa.Bd[2] = (const float*)d_in[16];
    sa.Wc[3] = (const float*)d_in[17]; sa.Ad[3] = (const float*)d_in[18]; sa.Bd[3] = (const float*)d_in[19];
    sa.Wc[4] = (const float*)d_in[20]; sa.Ad[4] = (const float*)d_in[21]; sa.Bd[4] = (const float*)d_in[22];
    sa.Wc[5] = (const float*)d_in[23]; sa.Ad[5] = (const float*)d_in[24]; sa.Bd[5] = (const float*)d_in[25];

    dim3 gg(BQ/128, NSPLIT);   // 16 x 8 = 128 CTAs

    // 1. integrate + 20-ch fluid feats
    k_prep<<<(BQ+127)/128, 128>>>(p0, v0, a, other, v0_enc);
    // 2. fused geometry + compaction + bin sort
    k_compact<<<BQ/8, 256>>>(p1, p1, fmask, list, cnt, boff);
    k_compact<<<BQ/8, 256>>>(box, p1, bmask, listo, cnto, boffo);
    // 3. stage-1 fluid binning (4th launch -> profiled)
    k_bin<40,1984,true><<<BQ, 240>>>(feats);
    // 4. obstacle binning + steered matrices
    k_bino<<<BQ, 128>>>(boxf);
    k_steer_all<<<(KS_TOTAL+255)/256, 256>>>(sa);
    // 5. stage 1 GEMM + fused finish (obstacle GEMM + partial reduce + nonlin)
    k_gemm_mma<<<gg, 128>>>(X, KS+OFF1A, 1984);
    k_fin1<<<(BQ*48+255)/256, 256>>>(KS+OFF1B);
    // 6. layer 1: 48 -> 32
    k_bin<96,4704,true><<<BQ, 240>>>(feats);
    k_gemm_mma<<<gg, 128>>>(X, KS+OFFL1, 4704);
    k_finnl<<<(BQ*32+255)/256, 256>>>(outB, nullptr);
    // 7. layer 2: 32 -> 32, residual
    k_bin<64,3136,true><<<BQ, 256>>>(feats);
    k_gemm_mma<<<gg, 128>>>(X, KS+OFFL2, 3136);
    k_finnl<<<(BQ*32+255)/256, 256>>>(outA, outB);
    // 8. layer 3: 32 -> 32, residual
    k_bin<64,3136,true><<<BQ, 256>>>(feats);
    k_gemm_mma<<<gg, 128>>>(X, KS+OFFL3, 3136);
    k_finnl<<<(BQ*32+255)/256, 256>>>(outB, outA);
    // 9. layer 4: 32 -> 1 (GEMV fused with final correction)
    k_bin<64,3136,false><<<BQ, 256>>>(feats);
    k_gemv_final<<<BQ/8, 256>>>(X, KS+OFFL4, 3136, p0, dout, half);
}

// round 9
// speedup vs baseline: 3.3110x; 1.0770x over previous
#include <cuda_runtime.h>
#include <math.h>
#include <stdint.h>

#define BB 4
#define NN 512
#define BQ 2048
#define KBINS 48
#define PI_F 3.14159265358979f
#define NSPLIT 8

typedef unsigned long long ull;

// ---------------- device scratch ----------------
__device__ __align__(16) float g_X[BQ * 4704];
__device__ __align__(16) float g_Xo[BQ * 96];
__device__ __align__(16) uint2 g_list [BQ * NN];
__device__ int   g_cnt [BQ];
__device__ int   g_boff[BQ * 49];
__device__ __align__(16) uint2 g_listo[BQ * NN];
__device__ int   g_cnto[BQ];
__device__ int   g_boffo[BQ * 49];
__device__ __align__(16) float g_KS[838784];
__device__ __align__(16) float g_part[NSPLIT * BQ * 64];
__device__ __align__(16) float g_outA[BQ * 96];
__device__ __align__(16) float g_outB[BQ * 96];
__device__ __align__(16) float g_feats[BQ * 96];
__device__ float g_p1[BQ * 2];

// KS segment offsets (floats) — contiguous prefix sums
#define OFF1A 0        // TC: 64 x 1984 (transposed, ld=1984)
#define OFF1B 126976   // row-major 96 x 32 (obstacle)
#define OFFL1 130048   // TC: 64 x 4704
#define OFFL2 431104   // TC: 64 x 3136
#define OFFL3 631808   // TC: 64 x 3136
#define OFFL4 832512   // row-major 3136 x 2 (gemv)
#define KS_TOTAL 838784

// ---------------- helpers ----------------
__device__ __forceinline__ float tf32r(float x) {
    uint32_t r; asm("cvt.rna.tf32.f32 %0, %1;" : "=r"(r) : "f"(x));
    return __uint_as_float(r);
}

// ---------------- kernels ----------------

__global__ void k_prep(const float* __restrict__ p0, const float* __restrict__ v0,
                       const float* __restrict__ a, const float* __restrict__ other,
                       const float* __restrict__ v0enc)
{
    int i = blockIdx.x*blockDim.x + threadIdx.x;
    if (i >= BQ) return;
    float v0x = v0[i*2], v0y = v0[i*2+1];
    float v1x = v0x + 0.1f*a[i*2], v1y = v0y + 0.1f*a[i*2+1];
    g_p1[i*2]   = p0[i*2]   + 0.05f*(v0x+v1x);
    g_p1[i*2+1] = p0[i*2+1] + 0.05f*(v0y+v1y);
    float* f = g_feats + i*40;
    f[0]=v1x; f[1]=v1y;
    #pragma unroll
    for (int c=0;c<3;c++){ f[2+c*2]=other[(i*3+c)*2]; f[3+c*2]=other[(i*3+c)*2+1]; }
    #pragma unroll
    for (int c=0;c<16;c++){ f[8+c*2]=v0enc[(i*16+c)*2]; f[9+c*2]=v0enc[(i*16+c)*2+1]; }
}

// geometry + compaction + stable counting sort by bin. One warp per query.
// blockIdx.y: 0 = fluid (src=qry=p1, fmask), 1 = obstacle (src=box, bmask).
__global__ void k_compact2(const float* __restrict__ box,
                           const float* __restrict__ fmask, const float* __restrict__ bmask,
                           uint2* __restrict__ listF, int* __restrict__ cntF, int* __restrict__ boffF,
                           uint2* __restrict__ listO, int* __restrict__ cntO, int* __restrict__ boffO)
{
    __shared__ uint2 s_tmp[8][NN];
    __shared__ int s_cnt[8][KBINS];
    __shared__ int s_off[8][KBINS+1];
    __shared__ int s_run[8][KBINS];
    int wIn = threadIdx.x >> 5;
    int lane = threadIdx.x & 31;
    int warp = blockIdx.x*8 + wIn;
    int b = warp >> 9, q = warp & 511;
    bool fluid = (blockIdx.y == 0);
    const float* src = fluid ? g_p1 : box;
    const float* mrow = (fluid ? fmask : bmask) + (size_t)warp*NN;
    uint2* list = fluid ? listF : listO;
    int* cnt  = fluid ? cntF : cntO;
    int* boff = fluid ? boffF : boffO;
    float qx = g_p1[(b*NN+q)*2], qy = g_p1[(b*NN+q)*2+1];
    for (int i = lane; i < KBINS; i += 32) { s_cnt[wIn][i] = 0; s_run[wIn][i] = 0; }
    __syncwarp();
    int base = 0;
    for (int c = 0; c < NN; c += 32) {
        int s = c + lane;
        float rx = src[(b*NN+s)*2]   - qx;
        float ry = src[(b*NN+s)*2+1] - qy;
        float d2 = rx*rx + ry*ry;
        float m = mrow[s];
        float win = 1.0f - d2*(1.0f/1600.0f);
        bool on = (win > 0.f) && (m != 0.f);
        float wv = 0.f; int kidx = 0;
        if (on) {
            wv = win*win*win*m;
            float dist = sqrtf(d2 + 1e-9f);
            int rb = (int)(dist*(3.0f/40.0f)); if (rb > 2) rb = 2;
            int tb = ((int)floorf((atan2f(ry,rx) + PI_F)*(16.0f/(2.0f*PI_F)))) & 15;
            kidx = rb*16 + tb;
        }
        unsigned mk = __ballot_sync(0xffffffffu, on);
        if (on) {
            int pos = base + __popc(mk & ((1u<<lane)-1u));
            s_tmp[wIn][pos] = make_uint2(__float_as_uint(wv), (unsigned)((kidx<<16) | s));
        }
        base += __popc(mk);
    }
    __syncwarp();
    for (int e = lane; e < base; e += 32)
        atomicAdd(&s_cnt[wIn][s_tmp[wIn][e].y >> 16], 1);
    __syncwarp();
    if (lane == 0) {
        int acc = 0;
        #pragma unroll
        for (int k = 0; k < KBINS; ++k) { s_off[wIn][k] = acc; acc += s_cnt[wIn][k]; }
        s_off[wIn][KBINS] = acc;
    }
    __syncwarp();
    uint2* lrow = list + (size_t)warp*NN;
    for (int c = 0; c < base; c += 32) {
        int e = c + lane;
        bool valid = e < base;
        unsigned msk = __ballot_sync(0xffffffffu, valid);
        int bin = 0, rank = 0, gcnt = 0; bool lead = false; uint2 pk;
        if (valid) {
            pk = s_tmp[wIn][e];
            bin = pk.y >> 16;
            unsigned grp = __match_any_sync(msk, bin);
            rank = __popc(grp & ((1u<<lane)-1u));
            lead = ((__ffs(grp)-1) == lane);
            gcnt = __popc(grp);
        }
        int runv = valid ? s_run[wIn][bin] : 0;
        __syncwarp();
        if (valid) {
            lrow[s_off[wIn][bin] + runv + rank] = pk;
            if (lead) s_run[wIn][bin] = runv + gcnt;
        }
        __syncwarp();
    }
    for (int k = lane; k < KBINS+1; k += 32) boff[warp*49 + k] = s_off[wIn][k];
    if (lane == 0) cnt[warp] = base;
}

// ---- steered-kernel assembly ----
struct SteerArgs { const float* Wc[6]; const float* Ad[6]; const float* Bd[6]; };

template<int O, int I, int COLS, int DOFF, int K, bool TC>
__device__ __forceinline__ float steer_val(int idx, const float* __restrict__ Wc,
                                           const float* __restrict__ Ad,
                                           const float* __restrict__ Bd,
                                           const float* tc, const float* ts)
{
    constexpr int IV = 2*I;
    int row, col;
    if (TC) { col = idx / K; row = idx - col*K; }
    else    { row = idx / COLS; col = idx - row*COLS; }
    float val = 0.f;
    if (row < KBINS*IV) {
        if (col < 2*O) {
            int k = row / IV, iv = row - k*IV, i = iv>>1, v = iv&1;
            int o = col>>1, u = col&1;
            int t = k & 15;
            float c = tc[t], s = ts[t];
            float R[2][2] = {{c,-s},{s,c}};
            const float* Wb = Wc + (((long long)k*O + o)*I + i)*4;
            val = R[u][0]*(Wb[0]*R[v][0] + Wb[1]*R[v][1])
                + R[u][1]*(Wb[2]*R[v][0] + Wb[3]*R[v][1]);
        }
    } else if (row < KBINS*IV + IV) {
        if (DOFF >= 0 && col >= DOFF && col < DOFF + 2*O) {
            int iv = row - KBINS*IV, i = iv>>1, v = iv&1;
            int oc = col - DOFF, o = oc>>1, u = oc&1;
            if (u == v) val = Ad[o*I+i];
            else        val = (u==0) ? -Bd[o*I+i] : Bd[o*I+i];
        }
    }
    return val;
}

__global__ void k_steer_all(SteerArgs args)
{
    __shared__ float tc[16], ts[16];
    if (threadIdx.x < 16) {
        float th = (threadIdx.x + 0.5f)*(2.0f*PI_F/16.0f) - PI_F;
        tc[threadIdx.x] = cosf(th);
        ts[threadIdx.x] = sinf(th);
    }
    __syncthreads();
    int gidx = blockIdx.x*blockDim.x + threadIdx.x;
    if (gidx >= KS_TOTAL) return;
    float val; bool rnd;
    if (gidx < OFF1B) {
        val = steer_val<16,20,64,32,1984,true>(gidx-OFF1A, args.Wc[0], args.Ad[0], args.Bd[0], tc, ts);
        rnd = true;
    } else if (gidx < OFFL1) {
        val = steer_val<16,1,32,-1,96,false>(gidx-OFF1B, args.Wc[1], 0, 0, tc, ts);
        rnd = false;
    } else if (gidx < OFFL2) {
        val = steer_val<32,48,64,0,4704,true>(gidx-OFFL1, args.Wc[2], args.Ad[2], args.Bd[2], tc, ts);
        rnd = true;
    } else if (gidx < OFFL3) {
        val = steer_val<32,32,64,0,3136,true>(gidx-OFFL2, args.Wc[3], args.Ad[3], args.Bd[3], tc, ts);
        rnd = true;
    } else if (gidx < OFFL4) {
        val = steer_val<32,32,64,0,3136,true>(gidx-OFFL3, args.Wc[4], args.Ad[4], args.Bd[4], tc, ts);
        rnd = true;
    } else {
        val = steer_val<1,32,2,0,3136,false>(gidx-OFFL4, args.Wc[5], args.Ad[5], args.Bd[5], tc, ts);
        rnd = false;
    }
    g_KS[gidx] = rnd ? tf32r(val) : val;
}

// ---- fluid binning body: sorted segments, dual register accumulators ----
template<int IV, int LD, bool RND, int NG>
__device__ __forceinline__ void bin_body(const float* __restrict__ feats)
{
    constexpr int HV = IV/2;
    constexpr int T = HV*NG;
    __shared__ uint2 sl[NN];
    __shared__ int sb[KBINS+1];
    int bq = blockIdx.x, tid = threadIdx.x, b = bq >> 9;
    int cnt = g_cnt[bq];
    const uint2* lrow = g_list + (size_t)bq*NN;
    for (int i = tid; i < cnt; i += T) sl[i] = lrow[i];
    for (int i = tid; i < KBINS+1; i += T) sb[i] = g_boff[bq*49 + i];
    __syncthreads();
    int col = tid % HV, grp = tid / HV;
    const float2* fb = (const float2*)feats + (size_t)(b*NN)*HV + col;
    float* xr = g_X + (size_t)bq*LD;
    for (int k = grp; k < KBINS; k += NG) {
        int e = sb[k], e1 = sb[k+1];
        float2 a0 = make_float2(0.f, 0.f), a1 = make_float2(0.f, 0.f);
        for (; e + 2 <= e1; e += 2) {
            uint2 p0 = sl[e], p1 = sl[e+1];
            float2 f0 = fb[(size_t)(p0.y & 0xffff)*HV];
            float2 f1 = fb[(size_t)(p1.y & 0xffff)*HV];
            float w0 = __uint_as_float(p0.x), w1 = __uint_as_float(p1.x);
            a0.x += w0*f0.x; a0.y += w0*f0.y;
            a1.x += w1*f1.x; a1.y += w1*f1.y;
        }
        if (e < e1) {
            uint2 p0 = sl[e];
            float2 f0 = fb[(size_t)(p0.y & 0xffff)*HV];
            float w0 = __uint_as_float(p0.x);
            a0.x += w0*f0.x; a0.y += w0*f0.y;
        }
        float2 acc = make_float2(a0.x + a1.x, a0.y + a1.y);
        if (RND) { acc.x = tf32r(acc.x); acc.y = tf32r(acc.y); }
        *(float2*)&xr[k*IV + 2*col] = acc;
    }
    for (int i = tid; i < IV; i += T) {
        float v = feats[(size_t)bq*IV + i];
        xr[KBINS*IV + i] = RND ? tf32r(v) : v;
    }
    for (int i = 49*IV + tid; i < LD; i += T) xr[i] = 0.f;
}

template<int IV, int LD, bool RND, int NG>
__global__ void k_bin(const float* __restrict__ feats)
{
    bin_body<IV, LD, RND, NG>(feats);
}

// obstacle binning body (sorted segments)
__device__ __forceinline__ void bino_body(const float* __restrict__ box_feats)
{
    __shared__ uint2 sl[NN];
    __shared__ float sbf[NN*2];
    __shared__ int sb[KBINS+1];
    int bq = blockIdx.x, tid = threadIdx.x, b = bq >> 9;
    int T = blockDim.x;
    int cnt = g_cnto[bq];
    const uint2* lrow = g_listo + (size_t)bq*NN;
    for (int i = tid; i < cnt; i += T) sl[i] = lrow[i];
    for (int i = tid; i < KBINS+1; i += T) sb[i] = g_boffo[bq*49 + i];
    for (int i = tid; i < NN*2; i += T) sbf[i] = box_feats[b*NN*2 + i];
    __syncthreads();
    if (tid < 96) {
        int k = tid >> 1, v = tid & 1;
        float acc = 0.f;
        int e1 = sb[k+1];
        for (int e = sb[k]; e < e1; ++e) {
            uint2 pk = sl[e];
            acc += __uint_as_float(pk.x) * sbf[(pk.y & 0xffff)*2 + v];
        }
        g_Xo[bq*96 + tid] = acc;
    }
}

// fused stage-1 binning: y==0 fluid bin<40>, y==1 obstacle
__global__ void k_bin1(const float* __restrict__ feats, const float* __restrict__ boxf)
{
    if (blockIdx.y == 0) bin_body<40, 1984, true, 12>(feats);
    else                 bino_body(boxf);
}

// ---- tensor-core GEMM via mma.sync tf32; BM=64 for 256-CTA coverage ----
__global__ void k_gemm_mma(const float* __restrict__ X, const float* __restrict__ Wt, int inner)
{
    __shared__ float As[64][36];
    __shared__ float Bs[64][36];
    int tid = threadIdx.x, lane = tid & 31, warp = tid >> 5;
    int row0 = blockIdx.x * 64;
    int ntiles = inner / 32;
    int per = (ntiles + NSPLIT - 1) / NSPLIT;
    int t0 = blockIdx.y * per;
    int t1 = min(ntiles, t0 + per);
    int g = lane >> 2, q = lane & 3;

    float acc[8][4];
    #pragma unroll
    for (int b = 0; b < 8; ++b)
        #pragma unroll
        for (int c = 0; c < 4; ++c) acc[b][c] = 0.f;

    for (int t = t0; t < t1; ++t) {
        int kk = t*32;
        #pragma unroll
        for (int r = 0; r < 4; ++r) {
            int idx = tid + r*128;
            int m = idx >> 3, c4 = (idx & 7)*4;
            float4 v = *(const float4*)&X[(size_t)(row0+m)*inner + kk + c4];
            *(float4*)&As[m][c4] = v;
        }
        #pragma unroll
        for (int r = 0; r < 4; ++r) {
            int idx = tid + r*128;
            int n = idx >> 3, c4 = (idx & 7)*4;
            float4 v = *(const float4*)&Wt[(size_t)n*inner + kk + c4];
            *(float4*)&Bs[n][c4] = v;
        }
        __syncthreads();
        #pragma unroll
        for (int k8 = 0; k8 < 4; ++k8) {
            int kb = k8*8;
            int mr = warp*16 + g;
            uint32_t a0 = __float_as_uint(As[mr][kb+q]);
            uint32_t a1 = __float_as_uint(As[mr+8][kb+q]);
            uint32_t a2 = __float_as_uint(As[mr][kb+q+4]);
            uint32_t a3 = __float_as_uint(As[mr+8][kb+q+4]);
            #pragma unroll
            for (int nt = 0; nt < 8; ++nt) {
                uint32_t b0 = __float_as_uint(Bs[nt*8 + g][kb + q]);
                uint32_t b1 = __float_as_uint(Bs[nt*8 + g][kb + q + 4]);
                asm volatile(
                    "mma.sync.aligned.m16n8k8.row.col.f32.tf32.tf32.f32 "
                    "{%0,%1,%2,%3}, {%4,%5,%6,%7}, {%8,%9}, {%0,%1,%2,%3};"
                    : "+f"(acc[nt][0]), "+f"(acc[nt][1]),
                      "+f"(acc[nt][2]), "+f"(acc[nt][3])
                    : "r"(a0), "r"(a1), "r"(a2), "r"(a3),
                      "r"(b0), "r"(b1));
            }
        }
        __syncthreads();
    }
    float* pb = g_part + ((size_t)blockIdx.y*BQ + row0)*64;
    int r0 = warp*16 + g;
    #pragma unroll
    for (int nt = 0; nt < 8; ++nt) {
        int c = nt*8 + q*2;
        *(float2*)&pb[(size_t)r0*64 + c]     = make_float2(acc[nt][0], acc[nt][1]);
        *(float2*)&pb[(size_t)(r0+8)*64 + c] = make_float2(acc[nt][2], acc[nt][3]);
    }
}

// ---- fused stage-1 finish: obstacle GEMM + fluid partial reduce + nonlin ----
__global__ void k_fin1(const float* __restrict__ KSo)
{
    int idx = blockIdx.x*blockDim.x + threadIdx.x;
    if (idx >= BQ*48) return;
    int row = idx / 48, ch = idx - row*48;
    float x = 0.f, y = 0.f;
    if (ch < 16) {
        const float* xr = g_Xo + row*96;
        #pragma unroll 8
        for (int k = 0; k < 96; ++k) {
            float xv = xr[k];
            x += xv * KSo[k*32 + 2*ch];
            y += xv * KSo[k*32 + 2*ch + 1];
        }
    } else {
        int c = ch - 16;
        #pragma unroll
        for (int s = 0; s < NSPLIT; ++s) {
            const float* p = g_part + ((size_t)s*BQ + row)*64 + 2*c;
            x += p[0]; y += p[1];
        }
    }
    float mag = x*x + y*y + 1e-6f;
    float sc = fmaxf(mag - 0.2f, 0.f) / mag;
    g_feats[row*96 + 2*ch]   = x*sc;
    g_feats[row*96 + 2*ch+1] = y*sc;
}

// fused: sum partials + residual + nonlinearity (64-col layers)
__global__ void k_finnl(float* __restrict__ out, const float* __restrict__ res)
{
    int idx = blockIdx.x*blockDim.x + threadIdx.x;
    if (idx >= BQ*32) return;
    int row = idx >> 5, c = idx & 31;
    float x = 0.f, y = 0.f;
    #pragma unroll
    for (int s = 0; s < NSPLIT; ++s) {
        const float* p = g_part + ((size_t)s*BQ + row)*64 + c*2;
        x += p[0]; y += p[1];
    }
    if (res) { x += res[row*64 + c*2]; y += res[row*64 + c*2+1]; }
    out[row*64 + c*2] = x; out[row*64 + c*2+1] = y;
    float mag = x*x + y*y + 1e-6f;
    float sc = fmaxf(mag - 0.2f, 0.f) / mag;
    g_feats[row*64 + c*2]   = x*sc;
    g_feats[row*64 + c*2+1] = y*sc;
}

// layer 4 GEMV fused with final correction
__global__ void k_gemv_final(const float* __restrict__ X, const float* __restrict__ Wm,
                             int inner, const float* __restrict__ p0,
                             float* __restrict__ dout, int half)
{
    __shared__ float Wsh[3136*2];
    int tid = threadIdx.x;
    for (int i = tid; i < inner*2; i += blockDim.x) Wsh[i] = Wm[i];
    __syncthreads();
    int warp = tid >> 5, lane = tid & 31;
    int row = blockIdx.x*8 + warp;
    const float* xr = X + (size_t)row*inner;
    float a0 = 0.f, a1 = 0.f;
    for (int k = lane; k < inner; k += 32) {
        float x = xr[k];
        a0 += x*Wsh[k*2];
        a1 += x*Wsh[k*2+1];
    }
    #pragma unroll
    for (int o = 16; o; o >>= 1) {
        a0 += __shfl_down_sync(0xffffffffu, a0, o);
        a1 += __shfl_down_sync(0xffffffffu, a1, o);
    }
    if (lane == 0) {
        float px = g_p1[row*2]   + a0*(1.0f/128.0f);
        float py = g_p1[row*2+1] + a1*(1.0f/128.0f);
        dout[row*2]   = px;
        dout[row*2+1] = py;
        dout[half + row*2]   = (px - p0[row*2])  *10.0f;
        dout[half + row*2+1] = (py - p0[row*2+1])*10.0f;
    }
}

// ---------------- host driver ----------------
extern "C" void kernel_launch(void* const* d_in, const int* in_sizes, int n_in,
                              void* d_out, int out_size)
{
    const float* v0_enc = (const float*)d_in[1];
    const float* p0     = (const float*)d_in[2];
    const float* v0     = (const float*)d_in[3];
    const float* a      = (const float*)d_in[4];
    const float* other  = (const float*)d_in[5];
    const float* box    = (const float*)d_in[6];
    const float* boxf   = (const float*)d_in[7];
    const float* fmask  = (const float*)d_in[8];
    const float* bmask  = (const float*)d_in[9];
    float* dout = (float*)d_out;
    int half = out_size / 2;

    float *X, *KS, *outA, *outB, *feats;
    uint2 *list, *listo; int *cnt, *cnto, *boff, *boffo;
    cudaGetSymbolAddress((void**)&X,     g_X);
    cudaGetSymbolAddress((void**)&KS,    g_KS);
    cudaGetSymbolAddress((void**)&outA,  g_outA);
    cudaGetSymbolAddress((void**)&outB,  g_outB);
    cudaGetSymbolAddress((void**)&feats, g_feats);
    cudaGetSymbolAddress((void**)&list,  g_list);
    cudaGetSymbolAddress((void**)&listo, g_listo);
    cudaGetSymbolAddress((void**)&cnt,   g_cnt);
    cudaGetSymbolAddress((void**)&cnto,  g_cnto);
    cudaGetSymbolAddress((void**)&boff,  g_boff);
    cudaGetSymbolAddress((void**)&boffo, g_boffo);

    SteerArgs sa;
    sa.Wc[0] = (const float*)d_in[10]; sa.Ad[0] = (const float*)d_in[12]; sa.Bd[0] = (const float*)d_in[13];
    sa.Wc[1] = (const float*)d_in[11]; sa.Ad[1] = nullptr;                sa.Bd[1] = nullptr;
    sa.Wc[2] = (const float*)d_in[14]; sa.Ad[2] = (const float*)d_in[15]; sa.Bd[2] = (const float*)d_in[16];
    sa.Wc[3] = (const float*)d_in[17]; sa.Ad[3] = (const float*)d_in[18]; sa.Bd[3] = (const float*)d_in[19];
    sa.Wc[4] = (const float*)d_in[20]; sa.Ad[4] = (const float*)d_in[21]; sa.Bd[4] = (const float*)d_in[22];
    sa.Wc[5] = (const float*)d_in[23]; sa.Ad[5] = (const float*)d_in[24]; sa.Bd[5] = (const float*)d_in[25];

    dim3 gg(BQ/64, NSPLIT);   // 32 x 8 = 256 CTAs

    // 1. integrate + 20-ch fluid feats
    k_prep<<<(BQ+127)/128, 128>>>(p0, v0, a, other, v0_enc);
    // 2. fused geometry + compaction + bin sort (fluid & obstacle in one launch)
    k_compact2<<<dim3(BQ/8, 2), 256>>>(box, fmask, bmask, list, cnt, boff, listo, cnto, boffo);
    // 3. steered matrices
    k_steer_all<<<(KS_TOTAL+255)/256, 256>>>(sa);
    // 4. stage-1 binning (fluid + obstacle fused; 4th launch -> profiled)
    k_bin1<<<dim3(BQ, 2), 240>>>(feats, boxf);
    // 5. stage 1 GEMM + fused finish
    k_gemm_mma<<<gg, 128>>>(X, KS+OFF1A, 1984);
    k_fin1<<<(BQ*48+255)/256, 256>>>(KS+OFF1B);
    // 6. layer 1: 48 -> 32
    k_bin<96,4704,true,6><<<BQ, 288>>>(feats);
    k_gemm_mma<<<gg, 128>>>(X, KS+OFFL1, 4704);
    k_finnl<<<(BQ*32+255)/256, 256>>>(outB, nullptr);
    // 7. layer 2: 32 -> 32, residual
    k_bin<64,3136,true,8><<<BQ, 256>>>(feats);
    k_gemm_mma<<<gg, 128>>>(X, KS+OFFL2, 3136);
    k_finnl<<<(BQ*32+255)/256, 256>>>(outA, outB);
    // 8. layer 3: 32 -> 32, residual
    k_bin<64,3136,true,8><<<BQ, 256>>>(feats);
    k_gemm_mma<<<gg, 128>>>(X, KS+OFFL3, 3136);
    k_finnl<<<(BQ*32+255)/256, 256>>>(outB, outA);
    // 9. layer 4: 32 -> 1 (GEMV fused with final correction)
    k_bin<64,3136,false,8><<<BQ, 256>>>(feats);
    k_gemv_final<<<BQ/8, 256>>>(X, KS+OFFL4, 3136, p0, dout, half);
}